// round 1
// baseline (speedup 1.0000x reference)
#include <cuda_runtime.h>
#include <cuda_bf16.h>
#include <math.h>

// Problem constants
#define BB 2
#define SS 2048
#define DD 2048
#define HH 16
#define NOPE 128
#define ROPE_D 64
#define VD 128
#define KV_RANK 512
#define Q_RANK 1536
#define QH (NOPE + ROPE_D)   // 192
#define KVH (NOPE + VD)      // 256
#define RTOT (BB * SS)       // 4096 rows

// ---------------- scratch (device globals, no allocation) ----------------
__device__ float g_cq [RTOT * Q_RANK];          // x @ w_dq, then rmsnorm in-place
__device__ float g_q  [RTOT * (HH * QH)];       // q (B,S,H,192), pe roped in-place
__device__ float g_ckv[RTOT * (KV_RANK + ROPE_D)];
__device__ float g_kva[RTOT * KV_RANK];         // rmsnorm(c_kv)
__device__ float g_kpe[RTOT * ROPE_D];          // roped k_pe
__device__ float g_kv [RTOT * (HH * KVH)];      // kv (B,S,H,256): [:128]=k_nope, [128:]=v
__device__ float g_o  [RTOT * (HH * VD)];       // attention out (B,S,H,128)
__device__ float g_cos[SS * (ROPE_D / 2)];
__device__ float g_sin[SS * (ROPE_D / 2)];

// ---------------- generic fp32 SGEMM: C = A(MxK) @ B(KxN), row-major ------
// 128x128 tile, BK=8, 256 threads, 8x8 per thread. Requires K % 8 == 0,
// N % 4 == 0. M,N guarded.
__global__ __launch_bounds__(256) void sgemm_k(
    const float* __restrict__ A, const float* __restrict__ B,
    float* __restrict__ C, int M, int N, int K)
{
    __shared__ float As[8][132];   // padded: conflict-free transposed stores
    __shared__ float Bs[8][128];

    const int n0 = blockIdx.x * 128;
    const int m0 = blockIdx.y * 128;
    const int tid = threadIdx.x;
    const int tx = tid & 15;
    const int ty = tid >> 4;

    const int aRow = tid >> 1;          // 0..127
    const int aK   = (tid & 1) * 4;     // 0 or 4
    const int bRow = tid >> 5;          // 0..7
    const int bCol = (tid & 31) * 4;    // 0..124

    float acc[8][8];
#pragma unroll
    for (int i = 0; i < 8; i++)
#pragma unroll
        for (int j = 0; j < 8; j++) acc[i][j] = 0.f;

    const float4 z4 = make_float4(0.f, 0.f, 0.f, 0.f);

    for (int k0 = 0; k0 < K; k0 += 8) {
        float4 a4 = (m0 + aRow < M)
            ? *(const float4*)(A + (size_t)(m0 + aRow) * K + k0 + aK) : z4;
        float4 b4 = (n0 + bCol < N)
            ? *(const float4*)(B + (size_t)(k0 + bRow) * N + n0 + bCol) : z4;

        As[aK + 0][aRow] = a4.x;
        As[aK + 1][aRow] = a4.y;
        As[aK + 2][aRow] = a4.z;
        As[aK + 3][aRow] = a4.w;
        *(float4*)&Bs[bRow][bCol] = b4;
        __syncthreads();

#pragma unroll
        for (int k = 0; k < 8; k++) {
            float4 a0 = *(const float4*)&As[k][4 * ty];
            float4 a1 = *(const float4*)&As[k][64 + 4 * ty];
            float4 b0 = *(const float4*)&Bs[k][4 * tx];
            float4 b1 = *(const float4*)&Bs[k][64 + 4 * tx];
            float rA[8] = {a0.x, a0.y, a0.z, a0.w, a1.x, a1.y, a1.z, a1.w};
            float rB[8] = {b0.x, b0.y, b0.z, b0.w, b1.x, b1.y, b1.z, b1.w};
#pragma unroll
            for (int i = 0; i < 8; i++)
#pragma unroll
                for (int j = 0; j < 8; j++)
                    acc[i][j] += rA[i] * rB[j];
        }
        __syncthreads();
    }

#pragma unroll
    for (int ih = 0; ih < 2; ih++) {
#pragma unroll
        for (int ii = 0; ii < 4; ii++) {
            int m = m0 + ih * 64 + 4 * ty + ii;
            if (m >= M) continue;
#pragma unroll
            for (int jh = 0; jh < 2; jh++) {
                int n = n0 + jh * 64 + 4 * tx;
                if (n < N) {
                    int i = ih * 4 + ii, j = jh * 4;
                    *(float4*)(C + (size_t)m * N + n) =
                        make_float4(acc[i][j], acc[i][j + 1], acc[i][j + 2], acc[i][j + 3]);
                }
            }
        }
    }
}

// ---------------- RMSNorm over `cols` with per-row strides ---------------
__global__ void rmsnorm_k(const float* in, float* out, const float* __restrict__ w,
                          int cols, int in_stride, int out_stride)
{
    const int row = blockIdx.x;
    const float* xi = in + (size_t)row * in_stride;
    float s = 0.f;
    for (int c = threadIdx.x; c < cols; c += blockDim.x) {
        float v = xi[c];
        s += v * v;
    }
    __shared__ float red[8];
#pragma unroll
    for (int o = 16; o > 0; o >>= 1) s += __shfl_down_sync(0xffffffffu, s, o);
    int warp = threadIdx.x >> 5, lane = threadIdx.x & 31;
    if (lane == 0) red[warp] = s;
    __syncthreads();
    if (warp == 0) {
        s = (lane < (blockDim.x >> 5)) ? red[lane] : 0.f;
#pragma unroll
        for (int o = 4; o > 0; o >>= 1) s += __shfl_down_sync(0xffffffffu, s, o);
        if (lane == 0) red[0] = s;
    }
    __syncthreads();
    float r = rsqrtf(red[0] / (float)cols + 1e-6f);
    float* yo = out + (size_t)row * out_stride;
    for (int c = threadIdx.x; c < cols; c += blockDim.x)
        yo[c] = xi[c] * r * w[c];
}

// ---------------- RoPE table (double precision angles, computed once) ----
__global__ void rope_table_k(float* ct, float* st)
{
    int s = blockIdx.x, i = threadIdx.x;                     // i in [0,32)
    double inv = exp(-((double)(2 * i) / 64.0) * log(10000.0));
    double ang = (double)s * inv;
    ct[s * 32 + i] = (float)cos(ang);
    st[s * 32 + i] = (float)sin(ang);
}

// RoPE applied in-place to the pe slice (last 64) of each q head
__global__ void rope_q_k(float* Q, const float* __restrict__ ct, const float* __restrict__ st)
{
    int bs = blockIdx.x;
    int s = bs & (SS - 1);
    int i = threadIdx.x;      // 0..31
    int h = threadIdx.y;      // 0..15
    size_t base = ((size_t)bs * HH + h) * QH + NOPE;
    float c = ct[s * 32 + i], sn = st[s * 32 + i];
    float x1 = Q[base + i], x2 = Q[base + 32 + i];
    Q[base + i]      = x1 * c - x2 * sn;
    Q[base + 32 + i] = x2 * c + x1 * sn;
}

// RoPE for k_pe (cols 512..575 of ckv) -> g_kpe
__global__ void rope_k_k(const float* __restrict__ CKV, float* KPE,
                         const float* __restrict__ ct, const float* __restrict__ st)
{
    int bs = blockIdx.x;
    int s = bs & (SS - 1);
    int i = threadIdx.x;
    const float* src = CKV + (size_t)bs * (KV_RANK + ROPE_D) + KV_RANK;
    float c = ct[s * 32 + i], sn = st[s * 32 + i];
    float x1 = src[i], x2 = src[32 + i];
    KPE[(size_t)bs * ROPE_D + i]      = x1 * c - x2 * sn;
    KPE[(size_t)bs * ROPE_D + 32 + i] = x2 * c + x1 * sn;
}

// ---------------- causal flash attention, fp32 ---------------------------
// One block = (b, h, 64-query tile). 64 threads, 1 thread = 1 query.
// smem: qs 64x196 (padded, private rows), ks 32x192, vs 32x128.
#define FBM 64
#define FBN 32
#define QS_STRIDE 196
#define FLASH_SMEM ((FBM * QS_STRIDE + FBN * QH + FBN * VD) * 4)

__global__ __launch_bounds__(64) void flash_k(
    const float* __restrict__ Q, const float* __restrict__ KV,
    const float* __restrict__ KPE, float* __restrict__ O)
{
    extern __shared__ float sm[];
    float* qs = sm;                          // FBM * 196
    float* ks = sm + FBM * QS_STRIDE;        // FBN * 192
    float* vs = ks + FBN * QH;               // FBN * 128

    const int q0 = blockIdx.x * FBM;
    const int h = blockIdx.y;
    const int b = blockIdx.z;
    const int t = threadIdx.x;
    const int qi = q0 + t;
    const float scale = 1.0f / sqrtf((float)QH);

    // load this thread's q row (private to this thread), pre-scaled
    {
        const float4* src = (const float4*)(Q + ((size_t)(b * SS + qi) * HH + h) * QH);
        float4* dst = (float4*)(qs + t * QS_STRIDE);
#pragma unroll
        for (int i = 0; i < QH / 4; i++) {
            float4 v = src[i];
            v.x *= scale; v.y *= scale; v.z *= scale; v.w *= scale;
            dst[i] = v;
        }
    }

    float acc[VD];
#pragma unroll
    for (int d = 0; d < VD; d++) acc[d] = 0.f;
    float mrun = -3.0e38f, lrun = 0.f;

    const int kend = q0 + FBM;   // causal: keys < q0+64 suffice for this tile
    for (int k0 = 0; k0 < kend; k0 += FBN) {
        __syncthreads();
        // cooperative K/V tile load: 2 threads per key row
        {
            int r = t >> 1, hf = t & 1;
            const float4* sn = (const float4*)(KV + ((size_t)(b * SS + k0 + r) * HH + h) * KVH);
            float4* dk = (float4*)(ks + r * QH);
#pragma unroll
            for (int i = 0; i < 16; i++) dk[hf * 16 + i] = sn[hf * 16 + i];          // k_nope 128
            const float4* sp = (const float4*)(KPE + (size_t)(b * SS + k0 + r) * ROPE_D);
#pragma unroll
            for (int i = 0; i < 8; i++) dk[32 + hf * 8 + i] = sp[hf * 8 + i];        // k_pe 64
            const float4* sv = sn + NOPE / 4;
            float4* dv = (float4*)(vs + r * VD);
#pragma unroll
            for (int i = 0; i < 16; i++) dv[hf * 16 + i] = sv[hf * 16 + i];          // v 128
        }
        __syncthreads();

        const float4* qp = (const float4*)(qs + t * QS_STRIDE);
        for (int jo = 0; jo < FBN; jo += 8) {
            float sj[8];
#pragma unroll
            for (int ji = 0; ji < 8; ji++) sj[ji] = 0.f;
            const float4* kp = (const float4*)(ks + jo * QH);
#pragma unroll 4
            for (int d4 = 0; d4 < QH / 4; d4++) {
                float4 a = qp[d4];
#pragma unroll
                for (int ji = 0; ji < 8; ji++) {
                    float4 kb = kp[ji * (QH / 4) + d4];
                    sj[ji] += a.x * kb.x + a.y * kb.y + a.z * kb.z + a.w * kb.w;
                }
            }
            // causal mask + running max. Note: first group (k0=0,jo=0) always
            // contains the unmasked key 0, so mrun is finite before any
            // fully-masked group is processed.
            float tmax = -3.0e38f;
#pragma unroll
            for (int ji = 0; ji < 8; ji++) {
                if (k0 + jo + ji > qi) sj[ji] = -3.0e38f;
                tmax = fmaxf(tmax, sj[ji]);
            }
            if (tmax > mrun) {
                float corr = __expf(mrun - tmax);
                lrun *= corr;
#pragma unroll
                for (int d = 0; d < VD; d++) acc[d] *= corr;
                mrun = tmax;
            }
            float pj[8];
#pragma unroll
            for (int ji = 0; ji < 8; ji++) {
                float p = __expf(sj[ji] - mrun);
                pj[ji] = p;
                lrun += p;
            }
#pragma unroll
            for (int d4 = 0; d4 < VD / 4; d4++) {
#pragma unroll
                for (int ji = 0; ji < 8; ji++) {
                    float4 v4 = ((const float4*)vs)[(jo + ji) * (VD / 4) + d4];
                    acc[4 * d4 + 0] += pj[ji] * v4.x;
                    acc[4 * d4 + 1] += pj[ji] * v4.y;
                    acc[4 * d4 + 2] += pj[ji] * v4.z;
                    acc[4 * d4 + 3] += pj[ji] * v4.w;
                }
            }
        }
    }

    float inv = 1.f / lrun;
    float4* dst = (float4*)(O + ((size_t)(b * SS + qi) * HH + h) * VD);
#pragma unroll
    for (int d4 = 0; d4 < VD / 4; d4++)
        dst[d4] = make_float4(acc[4 * d4] * inv, acc[4 * d4 + 1] * inv,
                              acc[4 * d4 + 2] * inv, acc[4 * d4 + 3] * inv);
}

// ---------------- host launcher ------------------------------------------
extern "C" void kernel_launch(void* const* d_in, const int* in_sizes, int n_in,
                              void* d_out, int out_size)
{
    const float* x         = (const float*)d_in[0];
    const float* w_dq      = (const float*)d_in[1];
    const float* q_a_norm  = (const float*)d_in[2];
    const float* w_uq      = (const float*)d_in[3];
    const float* w_dkv     = (const float*)d_in[4];
    const float* kv_a_norm = (const float*)d_in[5];
    const float* w_ukv     = (const float*)d_in[6];
    const float* w_o       = (const float*)d_in[7];
    float* out = (float*)d_out;

    float *cq, *q, *ckv, *kva, *kpe, *kv, *o, *ct, *st;
    cudaGetSymbolAddress((void**)&cq,  g_cq);
    cudaGetSymbolAddress((void**)&q,   g_q);
    cudaGetSymbolAddress((void**)&ckv, g_ckv);
    cudaGetSymbolAddress((void**)&kva, g_kva);
    cudaGetSymbolAddress((void**)&kpe, g_kpe);
    cudaGetSymbolAddress((void**)&kv,  g_kv);
    cudaGetSymbolAddress((void**)&o,   g_o);
    cudaGetSymbolAddress((void**)&ct,  g_cos);
    cudaGetSymbolAddress((void**)&st,  g_sin);

    cudaFuncSetAttribute(flash_k, cudaFuncAttributeMaxDynamicSharedMemorySize, FLASH_SMEM);

    // RoPE table (independent of everything else)
    rope_table_k<<<SS, 32>>>(ct, st);

    // q path: cq = x @ w_dq ; rmsnorm ; q = cq @ w_uq
    sgemm_k<<<dim3(Q_RANK / 128, RTOT / 128), 256>>>(x, w_dq, cq, RTOT, Q_RANK, DD);
    rmsnorm_k<<<RTOT, 256>>>(cq, cq, q_a_norm, Q_RANK, Q_RANK, Q_RANK);
    sgemm_k<<<dim3((HH * QH) / 128, RTOT / 128), 256>>>(cq, w_uq, q, RTOT, HH * QH, Q_RANK);

    // kv path: ckv = x @ w_dkv ; rmsnorm first 512 ; kv = kva @ w_ukv
    sgemm_k<<<dim3((KV_RANK + ROPE_D + 127) / 128, RTOT / 128), 256>>>(
        x, w_dkv, ckv, RTOT, KV_RANK + ROPE_D, DD);
    rmsnorm_k<<<RTOT, 256>>>(ckv, kva, kv_a_norm, KV_RANK, KV_RANK + ROPE_D, KV_RANK);
    sgemm_k<<<dim3((HH * KVH) / 128, RTOT / 128), 256>>>(kva, w_ukv, kv, RTOT, HH * KVH, KV_RANK);

    // RoPE
    rope_q_k<<<RTOT, dim3(32, HH)>>>(q, ct, st);
    rope_k_k<<<RTOT, 32>>>(ckv, kpe, ct, st);

    // attention
    flash_k<<<dim3(SS / FBM, HH, BB), 64, FLASH_SMEM>>>(q, kv, kpe, o);

    // output projection
    sgemm_k<<<dim3(DD / 128, RTOT / 128), 256>>>(o, w_o, out, RTOT, DD, HH * VD);
}

// round 2
// speedup vs baseline: 2.3666x; 2.3666x over previous
#include <cuda_runtime.h>
#include <cuda_bf16.h>
#include <math.h>

// Problem constants
#define BB 2
#define SS 2048
#define DD 2048
#define HH 16
#define NOPE 128
#define ROPE_D 64
#define VD 128
#define KV_RANK 512
#define Q_RANK 1536
#define QH (NOPE + ROPE_D)   // 192
#define KVH (NOPE + VD)      // 256
#define RTOT (BB * SS)       // 4096 rows

// ---------------- scratch (device globals, no allocation) ----------------
__device__ float g_cq [RTOT * Q_RANK];
__device__ float g_q  [RTOT * (HH * QH)];
__device__ float g_ckv[RTOT * (KV_RANK + ROPE_D)];
__device__ float g_kva[RTOT * KV_RANK];
__device__ float g_kpe[RTOT * ROPE_D];
__device__ float g_kv [RTOT * (HH * KVH)];
__device__ float g_o  [RTOT * (HH * VD)];
__device__ float g_cos[SS * (ROPE_D / 2)];
__device__ float g_sin[SS * (ROPE_D / 2)];

// ---------------- tf32 helpers -------------------------------------------
__device__ __forceinline__ unsigned f2tf32(float x) {
    unsigned r;
    asm("cvt.rna.tf32.f32 %0, %1;" : "=r"(r) : "f"(x));
    return r;
}

__device__ __forceinline__ void mma_tf32(float c[4], const unsigned a[4], const unsigned b[2]) {
    asm volatile(
        "mma.sync.aligned.m16n8k8.row.col.f32.tf32.tf32.f32 "
        "{%0,%1,%2,%3}, {%4,%5,%6,%7}, {%8,%9}, {%0,%1,%2,%3};\n"
        : "+f"(c[0]), "+f"(c[1]), "+f"(c[2]), "+f"(c[3])
        : "r"(a[0]), "r"(a[1]), "r"(a[2]), "r"(a[3]), "r"(b[0]), "r"(b[1]));
}

// ---------------- tf32 tensor-core GEMM: C = A(MxK) @ B(KxN), row-major ---
// 128x128 block tile, BK=32, 256 threads (8 warps as 2x4), warp tile 64x32.
// Requires M % 128 == 0, K % 32 == 0, N % 4 == 0 (N guarded).
#define TBM 128
#define TBN 128
#define TBK 32

__global__ __launch_bounds__(256) void tgemm_k(
    const float* __restrict__ A, const float* __restrict__ B,
    float* __restrict__ C, int M, int N, int K)
{
    __shared__ unsigned As[TBM][36];   // [m][k], pad -> conflict-free frag reads
    __shared__ unsigned Bs[TBK][136];  // [k][n], pad -> conflict-free frag reads

    const int n0 = blockIdx.x * TBN;
    const int m0 = blockIdx.y * TBM;
    const int tid  = threadIdx.x;
    const int lane = tid & 31;
    const int warp = tid >> 5;
    const int wm = warp & 1;           // 0..1
    const int wn = warp >> 1;          // 0..3
    const int g  = lane >> 2;          // 0..7
    const int tg = lane & 3;           // 0..3

    // global load indices
    const int aRow = tid >> 3;         // 0..31 (+32*s)
    const int aCol = (tid & 7) * 4;
    const int bRow = tid >> 5;         // 0..7 (+8*s)
    const int bCol = (tid & 31) * 4;

    float acc[4][4][4];
#pragma unroll
    for (int i = 0; i < 4; i++)
#pragma unroll
        for (int j = 0; j < 4; j++)
#pragma unroll
            for (int e = 0; e < 4; e++) acc[i][j][e] = 0.f;

    const float4 z4 = make_float4(0.f, 0.f, 0.f, 0.f);
    float4 ra[4], rb[4];

    // prologue: load k0 = 0
#pragma unroll
    for (int s = 0; s < 4; s++) {
        ra[s] = *(const float4*)(A + (size_t)(m0 + aRow + 32 * s) * K + aCol);
        rb[s] = (n0 + bCol < N)
            ? *(const float4*)(B + (size_t)(bRow + 8 * s) * N + n0 + bCol) : z4;
    }

    for (int k0 = 0; k0 < K; k0 += TBK) {
        // store current tile (converted to tf32)
#pragma unroll
        for (int s = 0; s < 4; s++) {
            unsigned av[4] = {f2tf32(ra[s].x), f2tf32(ra[s].y), f2tf32(ra[s].z), f2tf32(ra[s].w)};
            *(uint4*)&As[aRow + 32 * s][aCol] = *(uint4*)av;
            unsigned bv[4] = {f2tf32(rb[s].x), f2tf32(rb[s].y), f2tf32(rb[s].z), f2tf32(rb[s].w)};
            *(uint4*)&Bs[bRow + 8 * s][bCol] = *(uint4*)bv;
        }
        __syncthreads();

        // prefetch next tile into registers
        if (k0 + TBK < K) {
            const int kn = k0 + TBK;
#pragma unroll
            for (int s = 0; s < 4; s++) {
                ra[s] = *(const float4*)(A + (size_t)(m0 + aRow + 32 * s) * K + kn + aCol);
                rb[s] = (n0 + bCol < N)
                    ? *(const float4*)(B + (size_t)(kn + bRow + 8 * s) * N + n0 + bCol) : z4;
            }
        }

        // compute 4 k-steps of 8
#pragma unroll
        for (int kk = 0; kk < 4; kk++) {
            const int kr = kk * 8;
            unsigned af[4][4], bf[4][2];
#pragma unroll
            for (int i = 0; i < 4; i++) {
                const int r = wm * 64 + i * 16;
                af[i][0] = As[r + g][kr + tg];
                af[i][1] = As[r + g + 8][kr + tg];
                af[i][2] = As[r + g][kr + tg + 4];
                af[i][3] = As[r + g + 8][kr + tg + 4];
            }
#pragma unroll
            for (int j = 0; j < 4; j++) {
                const int cb = wn * 32 + j * 8;
                bf[j][0] = Bs[kr + tg][cb + g];
                bf[j][1] = Bs[kr + tg + 4][cb + g];
            }
#pragma unroll
            for (int i = 0; i < 4; i++)
#pragma unroll
                for (int j = 0; j < 4; j++)
                    mma_tf32(acc[i][j], af[i], bf[j]);
        }
        __syncthreads();
    }

    // epilogue
#pragma unroll
    for (int i = 0; i < 4; i++) {
        const int r0 = m0 + wm * 64 + i * 16 + g;
#pragma unroll
        for (int j = 0; j < 4; j++) {
            const int c = n0 + wn * 32 + j * 8 + 2 * tg;
            if (c < N) {
                *(float2*)(C + (size_t)r0 * N + c) = make_float2(acc[i][j][0], acc[i][j][1]);
                *(float2*)(C + (size_t)(r0 + 8) * N + c) = make_float2(acc[i][j][2], acc[i][j][3]);
            }
        }
    }
}

// ---------------- RMSNorm ------------------------------------------------
__global__ void rmsnorm_k(const float* in, float* out, const float* __restrict__ w,
                          int cols, int in_stride, int out_stride)
{
    const int row = blockIdx.x;
    const float* xi = in + (size_t)row * in_stride;
    float s = 0.f;
    for (int c = threadIdx.x; c < cols; c += blockDim.x) {
        float v = xi[c];
        s += v * v;
    }
    __shared__ float red[8];
#pragma unroll
    for (int o = 16; o > 0; o >>= 1) s += __shfl_down_sync(0xffffffffu, s, o);
    int warp = threadIdx.x >> 5, lane = threadIdx.x & 31;
    if (lane == 0) red[warp] = s;
    __syncthreads();
    if (warp == 0) {
        s = (lane < (blockDim.x >> 5)) ? red[lane] : 0.f;
#pragma unroll
        for (int o = 4; o > 0; o >>= 1) s += __shfl_down_sync(0xffffffffu, s, o);
        if (lane == 0) red[0] = s;
    }
    __syncthreads();
    float r = rsqrtf(red[0] / (float)cols + 1e-6f);
    float* yo = out + (size_t)row * out_stride;
    for (int c = threadIdx.x; c < cols; c += blockDim.x)
        yo[c] = xi[c] * r * w[c];
}

// ---------------- RoPE table ---------------------------------------------
__global__ void rope_table_k(float* ct, float* st)
{
    int s = blockIdx.x, i = threadIdx.x;                     // i in [0,32)
    double inv = exp(-((double)(2 * i) / 64.0) * log(10000.0));
    double ang = (double)s * inv;
    ct[s * 32 + i] = (float)cos(ang);
    st[s * 32 + i] = (float)sin(ang);
}

__global__ void rope_q_k(float* Q, const float* __restrict__ ct, const float* __restrict__ st)
{
    int bs = blockIdx.x;
    int s = bs & (SS - 1);
    int i = threadIdx.x;      // 0..31
    int h = threadIdx.y;      // 0..15
    size_t base = ((size_t)bs * HH + h) * QH + NOPE;
    float c = ct[s * 32 + i], sn = st[s * 32 + i];
    float x1 = Q[base + i], x2 = Q[base + 32 + i];
    Q[base + i]      = x1 * c - x2 * sn;
    Q[base + 32 + i] = x2 * c + x1 * sn;
}

__global__ void rope_k_k(const float* __restrict__ CKV, float* KPE,
                         const float* __restrict__ ct, const float* __restrict__ st)
{
    int bs = blockIdx.x;
    int s = bs & (SS - 1);
    int i = threadIdx.x;
    const float* src = CKV + (size_t)bs * (KV_RANK + ROPE_D) + KV_RANK;
    float c = ct[s * 32 + i], sn = st[s * 32 + i];
    float x1 = src[i], x2 = src[32 + i];
    KPE[(size_t)bs * ROPE_D + i]      = x1 * c - x2 * sn;
    KPE[(size_t)bs * ROPE_D + 32 + i] = x2 * c + x1 * sn;
}

// ---------------- causal flash attention, fp32, key-split ----------------
// One block = (b, h, 64-query tile). 128 threads: thread t handles query
// (t & 63); threads with t<64 process keys [0,16) of each 32-key tile,
// t>=64 process keys [16,32). Private (m,l,acc) merged via smem at the end.
#define FBM 64
#define FBN 32
#define QS_STRIDE 196
#define SCR_STRIDE 132
#define FLASH_SMEM ((FBM * QS_STRIDE + FBN * QH + FBN * VD) * 4)

__global__ __launch_bounds__(128) void flash_k(
    const float* __restrict__ Q, const float* __restrict__ KV,
    const float* __restrict__ KPE, float* __restrict__ O)
{
    extern __shared__ float sm[];
    float* qs = sm;                          // FBM * 196
    float* ks = sm + FBM * QS_STRIDE;        // FBN * 192
    float* vs = ks + FBN * QH;               // FBN * 128
    float* scratch = ks;                     // reused after main loop (64*132 <= 32*320)

    const int q0 = blockIdx.x * FBM;
    const int h = blockIdx.y;
    const int b = blockIdx.z;
    const int t = threadIdx.x;
    const int tq = t & 63;
    const int half = t >> 6;
    const int qi = q0 + tq;
    const float scale = rsqrtf((float)QH);

    // load q rows (t < 64 only; rows are per-query)
    if (t < 64) {
        const float4* src = (const float4*)(Q + ((size_t)(b * SS + qi) * HH + h) * QH);
        float4* dst = (float4*)(qs + tq * QS_STRIDE);
#pragma unroll
        for (int i = 0; i < QH / 4; i++) {
            float4 v = src[i];
            v.x *= scale; v.y *= scale; v.z *= scale; v.w *= scale;
            dst[i] = v;
        }
    }

    float acc[VD];
#pragma unroll
    for (int d = 0; d < VD; d++) acc[d] = 0.f;
    float mrun = -3.0e38f, lrun = 0.f;

    const int kend = q0 + FBM;
    for (int k0 = 0; k0 < kend; k0 += FBN) {
        __syncthreads();
        // cooperative K/V tile load: 4 threads per key row
        {
            int r = t >> 2, q4 = t & 3;
            const float4* sn = (const float4*)(KV + ((size_t)(b * SS + k0 + r) * HH + h) * KVH);
            const float4* sp = (const float4*)(KPE + (size_t)(b * SS + k0 + r) * ROPE_D);
            float4* dk = (float4*)(ks + r * QH);
#pragma unroll
            for (int i = 0; i < 12; i++) {
                int idx = q4 * 12 + i;
                dk[idx] = (idx < 32) ? sn[idx] : sp[idx - 32];
            }
            const float4* sv = sn + NOPE / 4;
            float4* dv = (float4*)(vs + r * VD);
#pragma unroll
            for (int i = 0; i < 8; i++) dv[q4 * 8 + i] = sv[q4 * 8 + i];
        }
        __syncthreads();

        const float4* qp = (const float4*)(qs + tq * QS_STRIDE);
        const int jbeg = half * 16;
        for (int jo = jbeg; jo < jbeg + 16; jo += 8) {
            float sj[8];
#pragma unroll
            for (int ji = 0; ji < 8; ji++) sj[ji] = 0.f;
            const float4* kp = (const float4*)(ks + jo * QH);
#pragma unroll 4
            for (int d4 = 0; d4 < QH / 4; d4++) {
                float4 a = qp[d4];
#pragma unroll
                for (int ji = 0; ji < 8; ji++) {
                    float4 kb = kp[ji * (QH / 4) + d4];
                    sj[ji] += a.x * kb.x + a.y * kb.y + a.z * kb.z + a.w * kb.w;
                }
            }
            float tmax = -3.0e38f;
#pragma unroll
            for (int ji = 0; ji < 8; ji++) {
                if (k0 + jo + ji > qi) sj[ji] = -3.0e38f;
                tmax = fmaxf(tmax, sj[ji]);
            }
            if (tmax > mrun) {
                float corr = __expf(mrun - tmax);
                lrun *= corr;
#pragma unroll
                for (int d = 0; d < VD; d++) acc[d] *= corr;
                mrun = tmax;
            }
            float pj[8];
#pragma unroll
            for (int ji = 0; ji < 8; ji++) {
                float p = __expf(sj[ji] - mrun);
                pj[ji] = p;
                lrun += p;
            }
#pragma unroll
            for (int d4 = 0; d4 < VD / 4; d4++) {
#pragma unroll
                for (int ji = 0; ji < 8; ji++) {
                    float4 v4 = ((const float4*)vs)[(jo + ji) * (VD / 4) + d4];
                    acc[4 * d4 + 0] += pj[ji] * v4.x;
                    acc[4 * d4 + 1] += pj[ji] * v4.y;
                    acc[4 * d4 + 2] += pj[ji] * v4.z;
                    acc[4 * d4 + 3] += pj[ji] * v4.w;
                }
            }
        }
    }

    // merge the two key-halves
    __syncthreads();
    if (half == 1) {
        float* sc = scratch + tq * SCR_STRIDE;
#pragma unroll
        for (int d4 = 0; d4 < VD / 4; d4++)
            *(float4*)(sc + 4 * d4) = make_float4(acc[4 * d4], acc[4 * d4 + 1],
                                                  acc[4 * d4 + 2], acc[4 * d4 + 3]);
        sc[128] = mrun;
        sc[129] = lrun;
    }
    __syncthreads();
    if (half == 0) {
        const float* sc = scratch + tq * SCR_STRIDE;
        float m2 = sc[128], l2 = sc[129];
        float m = fmaxf(mrun, m2);
        float c1 = __expf(mrun - m);
        float c2 = __expf(m2 - m);
        float inv = 1.f / (lrun * c1 + l2 * c2);
        float4* dst = (float4*)(O + ((size_t)(b * SS + qi) * HH + h) * VD);
#pragma unroll
        for (int d4 = 0; d4 < VD / 4; d4++) {
            float4 o2 = *(const float4*)(sc + 4 * d4);
            dst[d4] = make_float4((acc[4 * d4 + 0] * c1 + o2.x * c2) * inv,
                                  (acc[4 * d4 + 1] * c1 + o2.y * c2) * inv,
                                  (acc[4 * d4 + 2] * c1 + o2.z * c2) * inv,
                                  (acc[4 * d4 + 3] * c1 + o2.w * c2) * inv);
        }
    }
}

// ---------------- host launcher ------------------------------------------
extern "C" void kernel_launch(void* const* d_in, const int* in_sizes, int n_in,
                              void* d_out, int out_size)
{
    const float* x         = (const float*)d_in[0];
    const float* w_dq      = (const float*)d_in[1];
    const float* q_a_norm  = (const float*)d_in[2];
    const float* w_uq      = (const float*)d_in[3];
    const float* w_dkv     = (const float*)d_in[4];
    const float* kv_a_norm = (const float*)d_in[5];
    const float* w_ukv     = (const float*)d_in[6];
    const float* w_o       = (const float*)d_in[7];
    float* out = (float*)d_out;

    float *cq, *q, *ckv, *kva, *kpe, *kv, *o, *ct, *st;
    cudaGetSymbolAddress((void**)&cq,  g_cq);
    cudaGetSymbolAddress((void**)&q,   g_q);
    cudaGetSymbolAddress((void**)&ckv, g_ckv);
    cudaGetSymbolAddress((void**)&kva, g_kva);
    cudaGetSymbolAddress((void**)&kpe, g_kpe);
    cudaGetSymbolAddress((void**)&kv,  g_kv);
    cudaGetSymbolAddress((void**)&o,   g_o);
    cudaGetSymbolAddress((void**)&ct,  g_cos);
    cudaGetSymbolAddress((void**)&st,  g_sin);

    cudaFuncSetAttribute(flash_k, cudaFuncAttributeMaxDynamicSharedMemorySize, FLASH_SMEM);

    rope_table_k<<<SS, 32>>>(ct, st);

    // q path
    tgemm_k<<<dim3(Q_RANK / TBN, RTOT / TBM), 256>>>(x, w_dq, cq, RTOT, Q_RANK, DD);
    rmsnorm_k<<<RTOT, 256>>>(cq, cq, q_a_norm, Q_RANK, Q_RANK, Q_RANK);
    tgemm_k<<<dim3((HH * QH) / TBN, RTOT / TBM), 256>>>(cq, w_uq, q, RTOT, HH * QH, Q_RANK);

    // kv path
    tgemm_k<<<dim3((KV_RANK + ROPE_D + TBN - 1) / TBN, RTOT / TBM), 256>>>(
        x, w_dkv, ckv, RTOT, KV_RANK + ROPE_D, DD);
    rmsnorm_k<<<RTOT, 256>>>(ckv, kva, kv_a_norm, KV_RANK, KV_RANK + ROPE_D, KV_RANK);
    tgemm_k<<<dim3((HH * KVH) / TBN, RTOT / TBM), 256>>>(kva, w_ukv, kv, RTOT, HH * KVH, KV_RANK);

    // RoPE
    rope_q_k<<<RTOT, dim3(32, HH)>>>(q, ct, st);
    rope_k_k<<<RTOT, 32>>>(ckv, kpe, ct, st);

    // attention
    flash_k<<<dim3(SS / FBM, HH, BB), 128, FLASH_SMEM>>>(q, kv, kpe, o);

    // output projection
    tgemm_k<<<dim3(DD / TBN, RTOT / TBM), 256>>>(o, w_o, out, RTOT, DD, HH * VD);
}

// round 4
// speedup vs baseline: 4.2919x; 1.8135x over previous
#include <cuda_runtime.h>
#include <cuda_bf16.h>
#include <math.h>

// Problem constants
#define BB 2
#define SS 2048
#define DD 2048
#define HH 16
#define NOPE 128
#define ROPE_D 64
#define VD 128
#define KV_RANK 512
#define Q_RANK 1536
#define QH (NOPE + ROPE_D)   // 192
#define KVH (NOPE + VD)      // 256
#define RTOT (BB * SS)       // 4096 rows

// ---------------- scratch (device globals, no allocation) ----------------
__device__ float g_cq [RTOT * Q_RANK];
__device__ float g_q  [RTOT * (HH * QH)];
__device__ float g_ckv[RTOT * (KV_RANK + ROPE_D)];
__device__ float g_kva[RTOT * KV_RANK];
__device__ float g_kpe[RTOT * ROPE_D];
__device__ float g_kv [RTOT * (HH * KVH)];
__device__ float g_o  [RTOT * (HH * VD)];
__device__ float g_cos[SS * (ROPE_D / 2)];
__device__ float g_sin[SS * (ROPE_D / 2)];

// ---------------- tf32 helpers -------------------------------------------
__device__ __forceinline__ unsigned f2tf32(float x) {
    unsigned r;
    asm("cvt.rna.tf32.f32 %0, %1;" : "=r"(r) : "f"(x));
    return r;
}

__device__ __forceinline__ void mma_tf32(float c[4], const unsigned a[4], const unsigned b[2]) {
    asm volatile(
        "mma.sync.aligned.m16n8k8.row.col.f32.tf32.tf32.f32 "
        "{%0,%1,%2,%3}, {%4,%5,%6,%7}, {%8,%9}, {%0,%1,%2,%3};\n"
        : "+f"(c[0]), "+f"(c[1]), "+f"(c[2]), "+f"(c[3])
        : "r"(a[0]), "r"(a[1]), "r"(a[2]), "r"(a[3]), "r"(b[0]), "r"(b[1]));
}

// ---------------- tf32 tensor-core GEMM: C = A(MxK) @ B(KxN), row-major ---
#define TBM 128
#define TBN 128
#define TBK 32

__global__ __launch_bounds__(256) void tgemm_k(
    const float* __restrict__ A, const float* __restrict__ B,
    float* __restrict__ C, int M, int N, int K)
{
    __shared__ unsigned As[TBM][36];
    __shared__ unsigned Bs[TBK][136];

    const int n0 = blockIdx.x * TBN;
    const int m0 = blockIdx.y * TBM;
    const int tid  = threadIdx.x;
    const int lane = tid & 31;
    const int warp = tid >> 5;
    const int wm = warp & 1;
    const int wn = warp >> 1;
    const int g  = lane >> 2;
    const int tg = lane & 3;

    const int aRow = tid >> 3;
    const int aCol = (tid & 7) * 4;
    const int bRow = tid >> 5;
    const int bCol = (tid & 31) * 4;

    float acc[4][4][4];
#pragma unroll
    for (int i = 0; i < 4; i++)
#pragma unroll
        for (int j = 0; j < 4; j++)
#pragma unroll
            for (int e = 0; e < 4; e++) acc[i][j][e] = 0.f;

    const float4 z4 = make_float4(0.f, 0.f, 0.f, 0.f);
    float4 ra[4], rb[4];

#pragma unroll
    for (int s = 0; s < 4; s++) {
        ra[s] = *(const float4*)(A + (size_t)(m0 + aRow + 32 * s) * K + aCol);
        rb[s] = (n0 + bCol < N)
            ? *(const float4*)(B + (size_t)(bRow + 8 * s) * N + n0 + bCol) : z4;
    }

    for (int k0 = 0; k0 < K; k0 += TBK) {
#pragma unroll
        for (int s = 0; s < 4; s++) {
            unsigned av[4] = {f2tf32(ra[s].x), f2tf32(ra[s].y), f2tf32(ra[s].z), f2tf32(ra[s].w)};
            *(uint4*)&As[aRow + 32 * s][aCol] = *(uint4*)av;
            unsigned bv[4] = {f2tf32(rb[s].x), f2tf32(rb[s].y), f2tf32(rb[s].z), f2tf32(rb[s].w)};
            *(uint4*)&Bs[bRow + 8 * s][bCol] = *(uint4*)bv;
        }
        __syncthreads();

        if (k0 + TBK < K) {
            const int kn = k0 + TBK;
#pragma unroll
            for (int s = 0; s < 4; s++) {
                ra[s] = *(const float4*)(A + (size_t)(m0 + aRow + 32 * s) * K + kn + aCol);
                rb[s] = (n0 + bCol < N)
                    ? *(const float4*)(B + (size_t)(kn + bRow + 8 * s) * N + n0 + bCol) : z4;
            }
        }

#pragma unroll
        for (int kk = 0; kk < 4; kk++) {
            const int kr = kk * 8;
            unsigned af[4][4], bf[4][2];
#pragma unroll
            for (int i = 0; i < 4; i++) {
                const int r = wm * 64 + i * 16;
                af[i][0] = As[r + g][kr + tg];
                af[i][1] = As[r + g + 8][kr + tg];
                af[i][2] = As[r + g][kr + tg + 4];
                af[i][3] = As[r + g + 8][kr + tg + 4];
            }
#pragma unroll
            for (int j = 0; j < 4; j++) {
                const int cb = wn * 32 + j * 8;
                bf[j][0] = Bs[kr + tg][cb + g];
                bf[j][1] = Bs[kr + tg + 4][cb + g];
            }
#pragma unroll
            for (int i = 0; i < 4; i++)
#pragma unroll
                for (int j = 0; j < 4; j++)
                    mma_tf32(acc[i][j], af[i], bf[j]);
        }
        __syncthreads();
    }

#pragma unroll
    for (int i = 0; i < 4; i++) {
        const int r0 = m0 + wm * 64 + i * 16 + g;
#pragma unroll
        for (int j = 0; j < 4; j++) {
            const int c = n0 + wn * 32 + j * 8 + 2 * tg;
            if (c < N) {
                *(float2*)(C + (size_t)r0 * N + c) = make_float2(acc[i][j][0], acc[i][j][1]);
                *(float2*)(C + (size_t)(r0 + 8) * N + c) = make_float2(acc[i][j][2], acc[i][j][3]);
            }
        }
    }
}

// ---------------- RMSNorm ------------------------------------------------
__global__ void rmsnorm_k(const float* in, float* out, const float* __restrict__ w,
                          int cols, int in_stride, int out_stride)
{
    const int row = blockIdx.x;
    const float* xi = in + (size_t)row * in_stride;
    float s = 0.f;
    for (int c = threadIdx.x; c < cols; c += blockDim.x) {
        float v = xi[c];
        s += v * v;
    }
    __shared__ float red[8];
#pragma unroll
    for (int o = 16; o > 0; o >>= 1) s += __shfl_down_sync(0xffffffffu, s, o);
    int warp = threadIdx.x >> 5, lane = threadIdx.x & 31;
    if (lane == 0) red[warp] = s;
    __syncthreads();
    if (warp == 0) {
        s = (lane < (blockDim.x >> 5)) ? red[lane] : 0.f;
#pragma unroll
        for (int o = 4; o > 0; o >>= 1) s += __shfl_down_sync(0xffffffffu, s, o);
        if (lane == 0) red[0] = s;
    }
    __syncthreads();
    float r = rsqrtf(red[0] / (float)cols + 1e-6f);
    float* yo = out + (size_t)row * out_stride;
    for (int c = threadIdx.x; c < cols; c += blockDim.x)
        yo[c] = xi[c] * r * w[c];
}

// ---------------- RoPE ---------------------------------------------------
__global__ void rope_table_k(float* ct, float* st)
{
    int s = blockIdx.x, i = threadIdx.x;
    double inv = exp(-((double)(2 * i) / 64.0) * log(10000.0));
    double ang = (double)s * inv;
    ct[s * 32 + i] = (float)cos(ang);
    st[s * 32 + i] = (float)sin(ang);
}

__global__ void rope_q_k(float* Q, const float* __restrict__ ct, const float* __restrict__ st)
{
    int bs = blockIdx.x;
    int s = bs & (SS - 1);
    int i = threadIdx.x;
    int h = threadIdx.y;
    size_t base = ((size_t)bs * HH + h) * QH + NOPE;
    float c = ct[s * 32 + i], sn = st[s * 32 + i];
    float x1 = Q[base + i], x2 = Q[base + 32 + i];
    Q[base + i]      = x1 * c - x2 * sn;
    Q[base + 32 + i] = x2 * c + x1 * sn;
}

__global__ void rope_k_k(const float* __restrict__ CKV, float* KPE,
                         const float* __restrict__ ct, const float* __restrict__ st)
{
    int bs = blockIdx.x;
    int s = bs & (SS - 1);
    int i = threadIdx.x;
    const float* src = CKV + (size_t)bs * (KV_RANK + ROPE_D) + KV_RANK;
    float c = ct[s * 32 + i], sn = st[s * 32 + i];
    float x1 = src[i], x2 = src[32 + i];
    KPE[(size_t)bs * ROPE_D + i]      = x1 * c - x2 * sn;
    KPE[(size_t)bs * ROPE_D + 32 + i] = x2 * c + x1 * sn;
}

// ---------------- tf32 tensor-core causal flash attention ----------------
// Block: (b, h, 64-query tile). 128 threads = 4 warps; warp w owns query
// rows q0 + 16w + {g, g+8}. Q held as persistent A-fragments in registers.
// K (64x192) / V (64x128) staged to smem as tf32 each key tile. P goes
// through per-warp-private smem to become an A-fragment. O accumulated in
// fp32 C-fragments, online softmax per row via quad shuffles.
#define FBM 64
#define FBN 64
#define KS_STR 196
#define VS_STR 132
#define PS_STR 68
#define FLASH_SMEM ((FBN * KS_STR + FBN * VS_STR + FBM * PS_STR) * 4)

__global__ __launch_bounds__(128) void flash_k(
    const float* __restrict__ Q, const float* __restrict__ KV,
    const float* __restrict__ KPE, float* __restrict__ O)
{
    extern __shared__ unsigned smu[];
    unsigned* Ks = smu;                       // [64][196]
    unsigned* Vs = smu + FBN * KS_STR;        // [64][132]
    unsigned* Ps = Vs + FBN * VS_STR;         // [64][68]

    const int q0 = blockIdx.x * FBM;
    const int h = blockIdx.y;
    const int b = blockIdx.z;
    const int t = threadIdx.x;
    const int warp = t >> 5;
    const int lane = t & 31;
    const int g = lane >> 2;
    const int tg = lane & 3;
    const int row0 = warp * 16 + g;           // local query row (and +8)
    const float scale = rsqrtf((float)QH);

    // persistent Q fragments (rows q0+row0, q0+row0+8)
    unsigned aq[24][4];
    {
        const float* qp0 = Q + ((size_t)(b * SS + q0 + row0) * HH + h) * QH;
        const float* qp1 = qp0 + (size_t)8 * HH * QH;
#pragma unroll
        for (int kc = 0; kc < 24; kc++) {
            aq[kc][0] = f2tf32(qp0[kc * 8 + tg] * scale);
            aq[kc][1] = f2tf32(qp1[kc * 8 + tg] * scale);
            aq[kc][2] = f2tf32(qp0[kc * 8 + tg + 4] * scale);
            aq[kc][3] = f2tf32(qp1[kc * 8 + tg + 4] * scale);
        }
    }

    float oacc[16][4];
#pragma unroll
    for (int i = 0; i < 16; i++)
#pragma unroll
        for (int e = 0; e < 4; e++) oacc[i][e] = 0.f;
    float m0 = -3.0e38f, m1 = -3.0e38f, l0 = 0.f, l1 = 0.f;

    const int lr = t >> 1;      // key row this thread loads
    const int hf = t & 1;       // which half of the dims

    for (int tile = 0; tile <= blockIdx.x; tile++) {
        const int k0 = tile * FBN;
        __syncthreads();
        // cooperative K/V load (2 threads per key row), fp32 -> tf32
        {
            const float4* kn = (const float4*)(KV + ((size_t)(b * SS + k0 + lr) * HH + h) * KVH);
            const float4* kp = (const float4*)(KPE + (size_t)(b * SS + k0 + lr) * ROPE_D);
#pragma unroll
            for (int i = 0; i < 24; i++) {
                int d4 = hf * 24 + i;
                float4 v = (d4 < 32) ? kn[d4] : kp[d4 - 32];
                unsigned u[4] = {f2tf32(v.x), f2tf32(v.y), f2tf32(v.z), f2tf32(v.w)};
                *(uint4*)&Ks[lr * KS_STR + d4 * 4] = *(uint4*)u;
            }
#pragma unroll
            for (int i = 0; i < 16; i++) {
                int d4 = hf * 16 + i;
                float4 v = kn[32 + d4];
                unsigned u[4] = {f2tf32(v.x), f2tf32(v.y), f2tf32(v.z), f2tf32(v.w)};
                *(uint4*)&Vs[lr * VS_STR + d4 * 4] = *(uint4*)u;
            }
        }
        __syncthreads();

        if (k0 > q0 + warp * 16 + 15) continue;   // fully masked for this warp

        // QK^T
        float c[8][4];
#pragma unroll
        for (int nb = 0; nb < 8; nb++) {
#pragma unroll
            for (int e = 0; e < 4; e++) c[nb][e] = 0.f;
            const unsigned* krow = &Ks[(nb * 8 + g) * KS_STR];
#pragma unroll
            for (int kc = 0; kc < 24; kc++) {
                unsigned bf[2] = {krow[kc * 8 + tg], krow[kc * 8 + tg + 4]};
                mma_tf32(c[nb], aq[kc], bf);
            }
        }

        // causal mask (only tiles near the diagonal of this warp's rows)
        if (k0 + FBN - 1 > q0 + warp * 16) {
            const int r0g = q0 + warp * 16 + g;
#pragma unroll
            for (int nb = 0; nb < 8; nb++) {
                int col = k0 + nb * 8 + 2 * tg;
                if (col     > r0g)     c[nb][0] = -3.0e38f;
                if (col + 1 > r0g)     c[nb][1] = -3.0e38f;
                if (col     > r0g + 8) c[nb][2] = -3.0e38f;
                if (col + 1 > r0g + 8) c[nb][3] = -3.0e38f;
            }
        }

        // online softmax
        float tm0 = -3.0e38f, tm1 = -3.0e38f;
#pragma unroll
        for (int nb = 0; nb < 8; nb++) {
            tm0 = fmaxf(tm0, fmaxf(c[nb][0], c[nb][1]));
            tm1 = fmaxf(tm1, fmaxf(c[nb][2], c[nb][3]));
        }
        tm0 = fmaxf(tm0, __shfl_xor_sync(0xffffffffu, tm0, 1));
        tm0 = fmaxf(tm0, __shfl_xor_sync(0xffffffffu, tm0, 2));
        tm1 = fmaxf(tm1, __shfl_xor_sync(0xffffffffu, tm1, 1));
        tm1 = fmaxf(tm1, __shfl_xor_sync(0xffffffffu, tm1, 2));

        float nm0 = fmaxf(m0, tm0), nm1 = fmaxf(m1, tm1);
        float co0 = __expf(m0 - nm0), co1 = __expf(m1 - nm1);
        l0 *= co0; l1 *= co1;
#pragma unroll
        for (int nb = 0; nb < 16; nb++) {
            oacc[nb][0] *= co0; oacc[nb][1] *= co0;
            oacc[nb][2] *= co1; oacc[nb][3] *= co1;
        }
        m0 = nm0; m1 = nm1;

        unsigned* ps0 = &Ps[(size_t)(warp * 16 + g) * PS_STR];
        unsigned* ps1 = &Ps[(size_t)(warp * 16 + g + 8) * PS_STR];
        float ls0 = 0.f, ls1 = 0.f;
#pragma unroll
        for (int nb = 0; nb < 8; nb++) {
            float p0 = __expf(c[nb][0] - nm0);
            float p1 = __expf(c[nb][1] - nm0);
            float p2 = __expf(c[nb][2] - nm1);
            float p3 = __expf(c[nb][3] - nm1);
            ls0 += p0 + p1; ls1 += p2 + p3;
            ps0[nb * 8 + 2 * tg]     = f2tf32(p0);
            ps0[nb * 8 + 2 * tg + 1] = f2tf32(p1);
            ps1[nb * 8 + 2 * tg]     = f2tf32(p2);
            ps1[nb * 8 + 2 * tg + 1] = f2tf32(p3);
        }
        ls0 += __shfl_xor_sync(0xffffffffu, ls0, 1);
        ls0 += __shfl_xor_sync(0xffffffffu, ls0, 2);
        ls1 += __shfl_xor_sync(0xffffffffu, ls1, 1);
        ls1 += __shfl_xor_sync(0xffffffffu, ls1, 2);
        l0 += ls0; l1 += ls1;

        __syncwarp();

        // P @ V
#pragma unroll
        for (int kc = 0; kc < 8; kc++) {
            unsigned ap[4] = {ps0[kc * 8 + tg], ps1[kc * 8 + tg],
                              ps0[kc * 8 + tg + 4], ps1[kc * 8 + tg + 4]};
#pragma unroll
            for (int nb = 0; nb < 16; nb++) {
                unsigned bv[2] = {Vs[(kc * 8 + tg) * VS_STR + nb * 8 + g],
                                  Vs[(kc * 8 + tg + 4) * VS_STR + nb * 8 + g]};
                mma_tf32(oacc[nb], ap, bv);
            }
        }
        __syncwarp();
    }

    // epilogue
    float inv0 = 1.f / l0, inv1 = 1.f / l1;
    float* o0 = O + ((size_t)(b * SS + q0 + row0) * HH + h) * VD;
    float* o1 = o0 + (size_t)8 * HH * VD;
#pragma unroll
    for (int nb = 0; nb < 16; nb++) {
        *(float2*)(o0 + nb * 8 + 2 * tg) = make_float2(oacc[nb][0] * inv0, oacc[nb][1] * inv0);
        *(float2*)(o1 + nb * 8 + 2 * tg) = make_float2(oacc[nb][2] * inv1, oacc[nb][3] * inv1);
    }
}

// ---------------- host launcher ------------------------------------------
extern "C" void kernel_launch(void* const* d_in, const int* in_sizes, int n_in,
                              void* d_out, int out_size)
{
    const float* x         = (const float*)d_in[0];
    const float* w_dq      = (const float*)d_in[1];
    const float* q_a_norm  = (const float*)d_in[2];
    const float* w_uq      = (const float*)d_in[3];
    const float* w_dkv     = (const float*)d_in[4];
    const float* kv_a_norm = (const float*)d_in[5];
    const float* w_ukv     = (const float*)d_in[6];
    const float* w_o       = (const float*)d_in[7];
    float* out = (float*)d_out;

    float *cq, *q, *ckv, *kva, *kpe, *kv, *o, *ct, *st;
    cudaGetSymbolAddress((void**)&cq,  g_cq);
    cudaGetSymbolAddress((void**)&q,   g_q);
    cudaGetSymbolAddress((void**)&ckv, g_ckv);
    cudaGetSymbolAddress((void**)&kva, g_kva);
    cudaGetSymbolAddress((void**)&kpe, g_kpe);
    cudaGetSymbolAddress((void**)&kv,  g_kv);
    cudaGetSymbolAddress((void**)&o,   g_o);
    cudaGetSymbolAddress((void**)&ct,  g_cos);
    cudaGetSymbolAddress((void**)&st,  g_sin);

    cudaFuncSetAttribute(flash_k, cudaFuncAttributeMaxDynamicSharedMemorySize, FLASH_SMEM);

    rope_table_k<<<SS, 32>>>(ct, st);

    // q path
    tgemm_k<<<dim3(Q_RANK / TBN, RTOT / TBM), 256>>>(x, w_dq, cq, RTOT, Q_RANK, DD);
    rmsnorm_k<<<RTOT, 256>>>(cq, cq, q_a_norm, Q_RANK, Q_RANK, Q_RANK);
    tgemm_k<<<dim3((HH * QH) / TBN, RTOT / TBM), 256>>>(cq, w_uq, q, RTOT, HH * QH, Q_RANK);

    // kv path
    tgemm_k<<<dim3((KV_RANK + ROPE_D + TBN - 1) / TBN, RTOT / TBM), 256>>>(
        x, w_dkv, ckv, RTOT, KV_RANK + ROPE_D, DD);
    rmsnorm_k<<<RTOT, 256>>>(ckv, kva, kv_a_norm, KV_RANK, KV_RANK + ROPE_D, KV_RANK);
    tgemm_k<<<dim3((HH * KVH) / TBN, RTOT / TBM), 256>>>(kva, w_ukv, kv, RTOT, HH * KVH, KV_RANK);

    // RoPE
    rope_q_k<<<RTOT, dim3(32, HH)>>>(q, ct, st);
    rope_k_k<<<RTOT, 32>>>(ckv, kpe, ct, st);

    // attention
    flash_k<<<dim3(SS / FBM, HH, BB), 128, FLASH_SMEM>>>(q, kv, kpe, o);

    // output projection
    tgemm_k<<<dim3(DD / TBN, RTOT / TBM), 256>>>(o, w_o, out, RTOT, DD, HH * VD);
}

// round 5
// speedup vs baseline: 4.9729x; 1.1587x over previous
#include <cuda_runtime.h>
#include <cuda_bf16.h>
#include <math.h>

// Problem constants
#define BB 2
#define SS 2048
#define DD 2048
#define HH 16
#define NOPE 128
#define ROPE_D 64
#define VD 128
#define KV_RANK 512
#define Q_RANK 1536
#define QH (NOPE + ROPE_D)   // 192
#define KVH (NOPE + VD)      // 256
#define RTOT (BB * SS)       // 4096 rows

// ---------------- scratch (device globals, no allocation) ----------------
__device__ float g_cq [RTOT * Q_RANK];
__device__ float g_q  [RTOT * (HH * QH)];
__device__ float g_ckv[RTOT * (KV_RANK + ROPE_D)];
__device__ float g_kva[RTOT * KV_RANK];
__device__ float g_kpe[RTOT * ROPE_D];
__device__ float g_kv [RTOT * (HH * KVH)];
__device__ float g_o  [RTOT * (HH * VD)];
__device__ float g_cos[SS * (ROPE_D / 2)];
__device__ float g_sin[SS * (ROPE_D / 2)];

// ---------------- helpers -------------------------------------------------
__device__ __forceinline__ unsigned f2tf32(float x) {
    unsigned r;
    asm("cvt.rna.tf32.f32 %0, %1;" : "=r"(r) : "f"(x));
    return r;
}

__device__ __forceinline__ void mma_tf32(float c[4], const unsigned a[4], const unsigned b[2]) {
    asm volatile(
        "mma.sync.aligned.m16n8k8.row.col.f32.tf32.tf32.f32 "
        "{%0,%1,%2,%3}, {%4,%5,%6,%7}, {%8,%9}, {%0,%1,%2,%3};\n"
        : "+f"(c[0]), "+f"(c[1]), "+f"(c[2]), "+f"(c[3])
        : "r"(a[0]), "r"(a[1]), "r"(a[2]), "r"(a[3]), "r"(b[0]), "r"(b[1]));
}

__device__ __forceinline__ void cpasync16(void* dst_smem, const void* src) {
    unsigned d = (unsigned)__cvta_generic_to_shared(dst_smem);
    asm volatile("cp.async.cg.shared.global [%0], [%1], 16;\n" :: "r"(d), "l"(src));
}
#define CP_COMMIT() asm volatile("cp.async.commit_group;\n")
#define CP_WAIT(n)  asm volatile("cp.async.wait_group %0;\n" :: "n"(n))

// ---------------- tf32 tensor-core GEMM: C = A(MxK) @ B(KxN), row-major ---
// 128x128 block tile, BK=32, 128 threads (4 warps as 2x2), warp tile 64x64.
// Double-buffered smem fed by cp.async (raw fp32), tf32 convert on frag load.
// Requires M % 128 == 0, K % 32 == 0, N % 8 == 0 (N guarded via clamp).
#define TBM 128
#define TBN 128
#define TBK 32
#define AS_STR 36
#define BS_STR 136
#define AS_ELE (TBM * AS_STR)          // 4608 floats per buffer
#define BS_ELE (TBK * BS_STR)          // 4352 floats per buffer
#define TG_SMEM ((2 * AS_ELE + 2 * BS_ELE) * 4)

__global__ __launch_bounds__(128) void tgemm_k(
    const float* __restrict__ A, const float* __restrict__ B,
    float* __restrict__ C, int M, int N, int K)
{
    extern __shared__ float sm[];
    float* As[2] = {sm, sm + AS_ELE};
    float* Bs[2] = {sm + 2 * AS_ELE, sm + 2 * AS_ELE + BS_ELE};

    const int n0 = blockIdx.x * TBN;
    const int m0 = blockIdx.y * TBM;
    const int tid  = threadIdx.x;
    const int lane = tid & 31;
    const int warp = tid >> 5;
    const int wm = warp & 1;           // warp row (x64)
    const int wn = warp >> 1;          // warp col (x64)
    const int g  = lane >> 2;
    const int tg = lane & 3;

    // async-copy indices
    const int aRow  = tid >> 3;        // 0..15 (+16s)
    const int aCol4 = (tid & 7) * 4;
    const int bRow  = tid >> 5;        // 0..3 (+4s)
    const int bCol  = (tid & 31) * 4;
    const int bColC = (n0 + bCol < N) ? (n0 + bCol) : (N - 4);  // clamp (cols >= N never stored)

    float acc[4][8][4];
#pragma unroll
    for (int i = 0; i < 4; i++)
#pragma unroll
        for (int j = 0; j < 8; j++)
#pragma unroll
            for (int e = 0; e < 4; e++) acc[i][j][e] = 0.f;

    const int nt = K / TBK;

    // issue tile 0
    {
        const float* Asrc = A + (size_t)(m0 + aRow) * K + aCol4;
        float* Adst = As[0] + aRow * AS_STR + aCol4;
#pragma unroll
        for (int s = 0; s < 8; s++)
            cpasync16(Adst + s * 16 * AS_STR, Asrc + (size_t)s * 16 * K);
        const float* Bsrc = B + (size_t)bRow * N + bColC;
        float* Bdst = Bs[0] + bRow * BS_STR + bCol;
#pragma unroll
        for (int s = 0; s < 8; s++)
            cpasync16(Bdst + s * 4 * BS_STR, Bsrc + (size_t)s * 4 * N);
        CP_COMMIT();
    }

    for (int t = 0; t < nt; t++) {
        const int buf = t & 1;
        if (t + 1 < nt) {
            const int kn = (t + 1) * TBK;
            const float* Asrc = A + (size_t)(m0 + aRow) * K + kn + aCol4;
            float* Adst = As[buf ^ 1] + aRow * AS_STR + aCol4;
#pragma unroll
            for (int s = 0; s < 8; s++)
                cpasync16(Adst + s * 16 * AS_STR, Asrc + (size_t)s * 16 * K);
            const float* Bsrc = B + (size_t)(kn + bRow) * N + bColC;
            float* Bdst = Bs[buf ^ 1] + bRow * BS_STR + bCol;
#pragma unroll
            for (int s = 0; s < 8; s++)
                cpasync16(Bdst + s * 4 * BS_STR, Bsrc + (size_t)s * 4 * N);
            CP_COMMIT();
            CP_WAIT(1);
        } else {
            CP_WAIT(0);
        }
        __syncthreads();

        const float* Ab = As[buf];
        const float* Bb = Bs[buf];
#pragma unroll
        for (int kk = 0; kk < 4; kk++) {
            const int kr = kk * 8;
            unsigned af[4][4], bf[8][2];
#pragma unroll
            for (int i = 0; i < 4; i++) {
                const int r = wm * 64 + i * 16;
                af[i][0] = f2tf32(Ab[(r + g) * AS_STR + kr + tg]);
                af[i][1] = f2tf32(Ab[(r + g + 8) * AS_STR + kr + tg]);
                af[i][2] = f2tf32(Ab[(r + g) * AS_STR + kr + tg + 4]);
                af[i][3] = f2tf32(Ab[(r + g + 8) * AS_STR + kr + tg + 4]);
            }
#pragma unroll
            for (int j = 0; j < 8; j++) {
                const int cb = wn * 64 + j * 8;
                bf[j][0] = f2tf32(Bb[(kr + tg) * BS_STR + cb + g]);
                bf[j][1] = f2tf32(Bb[(kr + tg + 4) * BS_STR + cb + g]);
            }
#pragma unroll
            for (int i = 0; i < 4; i++)
#pragma unroll
                for (int j = 0; j < 8; j++)
                    mma_tf32(acc[i][j], af[i], bf[j]);
        }
        __syncthreads();
    }

    // epilogue
#pragma unroll
    for (int i = 0; i < 4; i++) {
        const int r0 = m0 + wm * 64 + i * 16 + g;
#pragma unroll
        for (int j = 0; j < 8; j++) {
            const int c = n0 + wn * 64 + j * 8 + 2 * tg;
            if (c < N) {
                *(float2*)(C + (size_t)r0 * N + c) = make_float2(acc[i][j][0], acc[i][j][1]);
                *(float2*)(C + (size_t)(r0 + 8) * N + c) = make_float2(acc[i][j][2], acc[i][j][3]);
            }
        }
    }
}

// ---------------- RMSNorm ------------------------------------------------
__global__ void rmsnorm_k(const float* in, float* out, const float* __restrict__ w,
                          int cols, int in_stride, int out_stride)
{
    const int row = blockIdx.x;
    const float* xi = in + (size_t)row * in_stride;
    float s = 0.f;
    for (int c = threadIdx.x; c < cols; c += blockDim.x) {
        float v = xi[c];
        s += v * v;
    }
    __shared__ float red[8];
#pragma unroll
    for (int o = 16; o > 0; o >>= 1) s += __shfl_down_sync(0xffffffffu, s, o);
    int warp = threadIdx.x >> 5, lane = threadIdx.x & 31;
    if (lane == 0) red[warp] = s;
    __syncthreads();
    if (warp == 0) {
        s = (lane < (blockDim.x >> 5)) ? red[lane] : 0.f;
#pragma unroll
        for (int o = 4; o > 0; o >>= 1) s += __shfl_down_sync(0xffffffffu, s, o);
        if (lane == 0) red[0] = s;
    }
    __syncthreads();
    float r = rsqrtf(red[0] / (float)cols + 1e-6f);
    float* yo = out + (size_t)row * out_stride;
    for (int c = threadIdx.x; c < cols; c += blockDim.x)
        yo[c] = xi[c] * r * w[c];
}

// ---------------- RoPE ---------------------------------------------------
__global__ void rope_table_k(float* ct, float* st)
{
    int s = blockIdx.x, i = threadIdx.x;
    double inv = exp(-((double)(2 * i) / 64.0) * log(10000.0));
    double ang = (double)s * inv;
    ct[s * 32 + i] = (float)cos(ang);
    st[s * 32 + i] = (float)sin(ang);
}

__global__ void rope_q_k(float* Q, const float* __restrict__ ct, const float* __restrict__ st)
{
    int bs = blockIdx.x;
    int s = bs & (SS - 1);
    int i = threadIdx.x;
    int h = threadIdx.y;
    size_t base = ((size_t)bs * HH + h) * QH + NOPE;
    float c = ct[s * 32 + i], sn = st[s * 32 + i];
    float x1 = Q[base + i], x2 = Q[base + 32 + i];
    Q[base + i]      = x1 * c - x2 * sn;
    Q[base + 32 + i] = x2 * c + x1 * sn;
}

__global__ void rope_k_k(const float* __restrict__ CKV, float* KPE,
                         const float* __restrict__ ct, const float* __restrict__ st)
{
    int bs = blockIdx.x;
    int s = bs & (SS - 1);
    int i = threadIdx.x;
    const float* src = CKV + (size_t)bs * (KV_RANK + ROPE_D) + KV_RANK;
    float c = ct[s * 32 + i], sn = st[s * 32 + i];
    float x1 = src[i], x2 = src[32 + i];
    KPE[(size_t)bs * ROPE_D + i]      = x1 * c - x2 * sn;
    KPE[(size_t)bs * ROPE_D + 32 + i] = x2 * c + x1 * sn;
}

// ---------------- tf32 tensor-core causal flash attention ----------------
// Block: (b, h, 128-query tile). 256 threads = 8 warps; warp w owns query
// rows q0 + 16w + {g, g+8}. Q persistent in registers as A-fragments.
// K (64x192) / V (64x128) staged to smem as tf32 per 64-key tile.
#define FBM 128
#define FBN 64
#define KS_STR 196
#define VS_STR 136
#define PS_STR 68
#define FLASH_SMEM ((FBN * KS_STR + FBN * VS_STR + FBM * PS_STR) * 4)

__global__ __launch_bounds__(256) void flash_k(
    const float* __restrict__ Q, const float* __restrict__ KV,
    const float* __restrict__ KPE, float* __restrict__ O)
{
    extern __shared__ unsigned smu[];
    unsigned* Ks = smu;                       // [64][196]
    unsigned* Vs = smu + FBN * KS_STR;        // [64][136]
    unsigned* Ps = Vs + FBN * VS_STR;         // [128][68]

    const int q0 = blockIdx.x * FBM;
    const int h = blockIdx.y;
    const int b = blockIdx.z;
    const int t = threadIdx.x;
    const int warp = t >> 5;
    const int lane = t & 31;
    const int g = lane >> 2;
    const int tg = lane & 3;
    const int row0 = warp * 16 + g;           // local query row (and +8)
    const float scale = rsqrtf((float)QH);

    // persistent Q fragments (rows q0+row0, q0+row0+8)
    unsigned aq[24][4];
    {
        const float* qp0 = Q + ((size_t)(b * SS + q0 + row0) * HH + h) * QH;
        const float* qp1 = qp0 + (size_t)8 * HH * QH;
#pragma unroll
        for (int kc = 0; kc < 24; kc++) {
            aq[kc][0] = f2tf32(qp0[kc * 8 + tg] * scale);
            aq[kc][1] = f2tf32(qp1[kc * 8 + tg] * scale);
            aq[kc][2] = f2tf32(qp0[kc * 8 + tg + 4] * scale);
            aq[kc][3] = f2tf32(qp1[kc * 8 + tg + 4] * scale);
        }
    }

    float oacc[16][4];
#pragma unroll
    for (int i = 0; i < 16; i++)
#pragma unroll
        for (int e = 0; e < 4; e++) oacc[i][e] = 0.f;
    float m0 = -3.0e38f, m1 = -3.0e38f, l0 = 0.f, l1 = 0.f;

    const int lr = t >> 2;      // key row this thread loads (0..63)
    const int q4 = t & 3;       // quarter of the dims

    for (int k0 = 0; k0 < q0 + FBM; k0 += FBN) {
        __syncthreads();
        // cooperative K/V load (4 threads per key row), fp32 -> tf32
        {
            const float4* kn = (const float4*)(KV + ((size_t)(b * SS + k0 + lr) * HH + h) * KVH);
            const float4* kp = (const float4*)(KPE + (size_t)(b * SS + k0 + lr) * ROPE_D);
#pragma unroll
            for (int i = 0; i < 12; i++) {
                int d4 = q4 * 12 + i;
                float4 v = (d4 < 32) ? kn[d4] : kp[d4 - 32];
                unsigned u[4] = {f2tf32(v.x), f2tf32(v.y), f2tf32(v.z), f2tf32(v.w)};
                *(uint4*)&Ks[lr * KS_STR + d4 * 4] = *(uint4*)u;
            }
#pragma unroll
            for (int i = 0; i < 8; i++) {
                int d4 = q4 * 8 + i;
                float4 v = kn[32 + d4];
                unsigned u[4] = {f2tf32(v.x), f2tf32(v.y), f2tf32(v.z), f2tf32(v.w)};
                *(uint4*)&Vs[lr * VS_STR + d4 * 4] = *(uint4*)u;
            }
        }
        __syncthreads();

        if (k0 > q0 + warp * 16 + 15) continue;   // fully masked for this warp

        // QK^T
        float c[8][4];
#pragma unroll
        for (int nb = 0; nb < 8; nb++) {
#pragma unroll
            for (int e = 0; e < 4; e++) c[nb][e] = 0.f;
            const unsigned* krow = &Ks[(nb * 8 + g) * KS_STR];
#pragma unroll
            for (int kc = 0; kc < 24; kc++) {
                unsigned bf[2] = {krow[kc * 8 + tg], krow[kc * 8 + tg + 4]};
                mma_tf32(c[nb], aq[kc], bf);
            }
        }

        // causal mask (only near-diagonal tiles for this warp)
        if (k0 + FBN - 1 > q0 + warp * 16) {
            const int r0g = q0 + warp * 16 + g;
#pragma unroll
            for (int nb = 0; nb < 8; nb++) {
                int col = k0 + nb * 8 + 2 * tg;
                if (col     > r0g)     c[nb][0] = -3.0e38f;
                if (col + 1 > r0g)     c[nb][1] = -3.0e38f;
                if (col     > r0g + 8) c[nb][2] = -3.0e38f;
                if (col + 1 > r0g + 8) c[nb][3] = -3.0e38f;
            }
        }

        // online softmax
        float tm0 = -3.0e38f, tm1 = -3.0e38f;
#pragma unroll
        for (int nb = 0; nb < 8; nb++) {
            tm0 = fmaxf(tm0, fmaxf(c[nb][0], c[nb][1]));
            tm1 = fmaxf(tm1, fmaxf(c[nb][2], c[nb][3]));
        }
        tm0 = fmaxf(tm0, __shfl_xor_sync(0xffffffffu, tm0, 1));
        tm0 = fmaxf(tm0, __shfl_xor_sync(0xffffffffu, tm0, 2));
        tm1 = fmaxf(tm1, __shfl_xor_sync(0xffffffffu, tm1, 1));
        tm1 = fmaxf(tm1, __shfl_xor_sync(0xffffffffu, tm1, 2));

        float nm0 = fmaxf(m0, tm0), nm1 = fmaxf(m1, tm1);
        float co0 = __expf(m0 - nm0), co1 = __expf(m1 - nm1);
        l0 *= co0; l1 *= co1;
#pragma unroll
        for (int nb = 0; nb < 16; nb++) {
            oacc[nb][0] *= co0; oacc[nb][1] *= co0;
            oacc[nb][2] *= co1; oacc[nb][3] *= co1;
        }
        m0 = nm0; m1 = nm1;

        unsigned* ps0 = &Ps[(size_t)(warp * 16 + g) * PS_STR];
        unsigned* ps1 = &Ps[(size_t)(warp * 16 + g + 8) * PS_STR];
        float ls0 = 0.f, ls1 = 0.f;
#pragma unroll
        for (int nb = 0; nb < 8; nb++) {
            float p0 = __expf(c[nb][0] - nm0);
            float p1 = __expf(c[nb][1] - nm0);
            float p2 = __expf(c[nb][2] - nm1);
            float p3 = __expf(c[nb][3] - nm1);
            ls0 += p0 + p1; ls1 += p2 + p3;
            ps0[nb * 8 + 2 * tg]     = f2tf32(p0);
            ps0[nb * 8 + 2 * tg + 1] = f2tf32(p1);
            ps1[nb * 8 + 2 * tg]     = f2tf32(p2);
            ps1[nb * 8 + 2 * tg + 1] = f2tf32(p3);
        }
        ls0 += __shfl_xor_sync(0xffffffffu, ls0, 1);
        ls0 += __shfl_xor_sync(0xffffffffu, ls0, 2);
        ls1 += __shfl_xor_sync(0xffffffffu, ls1, 1);
        ls1 += __shfl_xor_sync(0xffffffffu, ls1, 2);
        l0 += ls0; l1 += ls1;

        __syncwarp();

        // P @ V
#pragma unroll
        for (int kc = 0; kc < 8; kc++) {
            unsigned ap[4] = {ps0[kc * 8 + tg], ps1[kc * 8 + tg],
                              ps0[kc * 8 + tg + 4], ps1[kc * 8 + tg + 4]};
#pragma unroll
            for (int nb = 0; nb < 16; nb++) {
                unsigned bv[2] = {Vs[(kc * 8 + tg) * VS_STR + nb * 8 + g],
                                  Vs[(kc * 8 + tg + 4) * VS_STR + nb * 8 + g]};
                mma_tf32(oacc[nb], ap, bv);
            }
        }
        __syncwarp();
    }

    // epilogue
    float inv0 = 1.f / l0, inv1 = 1.f / l1;
    float* o0 = O + ((size_t)(b * SS + q0 + row0) * HH + h) * VD;
    float* o1 = o0 + (size_t)8 * HH * VD;
#pragma unroll
    for (int nb = 0; nb < 16; nb++) {
        *(float2*)(o0 + nb * 8 + 2 * tg) = make_float2(oacc[nb][0] * inv0, oacc[nb][1] * inv0);
        *(float2*)(o1 + nb * 8 + 2 * tg) = make_float2(oacc[nb][2] * inv1, oacc[nb][3] * inv1);
    }
}

// ---------------- host launcher ------------------------------------------
extern "C" void kernel_launch(void* const* d_in, const int* in_sizes, int n_in,
                              void* d_out, int out_size)
{
    const float* x         = (const float*)d_in[0];
    const float* w_dq      = (const float*)d_in[1];
    const float* q_a_norm  = (const float*)d_in[2];
    const float* w_uq      = (const float*)d_in[3];
    const float* w_dkv     = (const float*)d_in[4];
    const float* kv_a_norm = (const float*)d_in[5];
    const float* w_ukv     = (const float*)d_in[6];
    const float* w_o       = (const float*)d_in[7];
    float* out = (float*)d_out;

    float *cq, *q, *ckv, *kva, *kpe, *kv, *o, *ct, *st;
    cudaGetSymbolAddress((void**)&cq,  g_cq);
    cudaGetSymbolAddress((void**)&q,   g_q);
    cudaGetSymbolAddress((void**)&ckv, g_ckv);
    cudaGetSymbolAddress((void**)&kva, g_kva);
    cudaGetSymbolAddress((void**)&kpe, g_kpe);
    cudaGetSymbolAddress((void**)&kv,  g_kv);
    cudaGetSymbolAddress((void**)&o,   g_o);
    cudaGetSymbolAddress((void**)&ct,  g_cos);
    cudaGetSymbolAddress((void**)&st,  g_sin);

    cudaFuncSetAttribute(tgemm_k, cudaFuncAttributeMaxDynamicSharedMemorySize, TG_SMEM);
    cudaFuncSetAttribute(flash_k, cudaFuncAttributeMaxDynamicSharedMemorySize, FLASH_SMEM);

    rope_table_k<<<SS, 32>>>(ct, st);

    // q path
    tgemm_k<<<dim3(Q_RANK / TBN, RTOT / TBM), 128, TG_SMEM>>>(x, w_dq, cq, RTOT, Q_RANK, DD);
    rmsnorm_k<<<RTOT, 256>>>(cq, cq, q_a_norm, Q_RANK, Q_RANK, Q_RANK);
    tgemm_k<<<dim3((HH * QH) / TBN, RTOT / TBM), 128, TG_SMEM>>>(cq, w_uq, q, RTOT, HH * QH, Q_RANK);

    // kv path
    tgemm_k<<<dim3((KV_RANK + ROPE_D + TBN - 1) / TBN, RTOT / TBM), 128, TG_SMEM>>>(
        x, w_dkv, ckv, RTOT, KV_RANK + ROPE_D, DD);
    rmsnorm_k<<<RTOT, 256>>>(ckv, kva, kv_a_norm, KV_RANK, KV_RANK + ROPE_D, KV_RANK);
    tgemm_k<<<dim3((HH * KVH) / TBN, RTOT / TBM), 128, TG_SMEM>>>(kva, w_ukv, kv, RTOT, HH * KVH, KV_RANK);

    // RoPE
    rope_q_k<<<RTOT, dim3(32, HH)>>>(q, ct, st);
    rope_k_k<<<RTOT, 32>>>(ckv, kpe, ct, st);

    // attention
    flash_k<<<dim3(SS / FBM, HH, BB), 256, FLASH_SMEM>>>(q, kv, kpe, o);

    // output projection
    tgemm_k<<<dim3(DD / TBN, RTOT / TBM), 128, TG_SMEM>>>(o, w_o, out, RTOT, DD, HH * VD);
}

// round 8
// speedup vs baseline: 5.1957x; 1.0448x over previous
#include <cuda_runtime.h>
#include <cuda_bf16.h>
#include <math.h>

// Problem constants
#define BB 2
#define SS 2048
#define DD 2048
#define HH 16
#define NOPE 128
#define ROPE_D 64
#define VD 128
#define KV_RANK 512
#define Q_RANK 1536
#define QH (NOPE + ROPE_D)   // 192
#define KVH (NOPE + VD)      // 256
#define RTOT (BB * SS)       // 4096 rows

// ---------------- scratch (device globals, no allocation) ----------------
__device__ float g_cq [RTOT * Q_RANK];
__device__ float g_q  [RTOT * (HH * QH)];
__device__ float g_ckv[RTOT * (KV_RANK + ROPE_D)];
__device__ float g_kva[RTOT * KV_RANK];
__device__ float g_kpe[RTOT * ROPE_D];
__device__ float g_kv [RTOT * (HH * KVH)];
__device__ float g_o  [RTOT * (HH * VD)];
__device__ float g_cos[SS * (ROPE_D / 2)];
__device__ float g_sin[SS * (ROPE_D / 2)];
// tf32-rounded operand copies
__device__ float g_xr  [RTOT * DD];
__device__ float g_wdq [DD * Q_RANK];
__device__ float g_wuq [Q_RANK * HH * QH];
__device__ float g_wdkv[DD * (KV_RANK + ROPE_D)];
__device__ float g_wukv[KV_RANK * HH * KVH];
__device__ float g_wo  [HH * VD * DD];

// ---------------- helpers -------------------------------------------------
__device__ __forceinline__ unsigned f2tf32(float x) {
    unsigned r;
    asm("cvt.rna.tf32.f32 %0, %1;" : "=r"(r) : "f"(x));
    return r;
}
__device__ __forceinline__ float roundtf(float x) {
    return __uint_as_float(f2tf32(x));
}

__device__ __forceinline__ void mma_tf32(float c[4], const unsigned a[4], const unsigned b[2]) {
    asm volatile(
        "mma.sync.aligned.m16n8k8.row.col.f32.tf32.tf32.f32 "
        "{%0,%1,%2,%3}, {%4,%5,%6,%7}, {%8,%9}, {%0,%1,%2,%3};\n"
        : "+f"(c[0]), "+f"(c[1]), "+f"(c[2]), "+f"(c[3])
        : "r"(a[0]), "r"(a[1]), "r"(a[2]), "r"(a[3]), "r"(b[0]), "r"(b[1]));
}

__device__ __forceinline__ void cpasync16(void* dst_smem, const void* src) {
    unsigned d = (unsigned)__cvta_generic_to_shared(dst_smem);
    asm volatile("cp.async.cg.shared.global [%0], [%1], 16;\n" :: "r"(d), "l"(src));
}
#define CP_COMMIT() asm volatile("cp.async.commit_group;\n")
#define CP_WAIT(n)  asm volatile("cp.async.wait_group %0;\n" :: "n"(n))

// ---------------- tf32 pre-round pass ------------------------------------
__global__ void cvt_k(const float4* __restrict__ in, float4* __restrict__ out, int n4)
{
    int i = blockIdx.x * blockDim.x + threadIdx.x;
    int stride = gridDim.x * blockDim.x;
    for (; i < n4; i += stride) {
        float4 v = in[i];
        v.x = roundtf(v.x); v.y = roundtf(v.y);
        v.z = roundtf(v.z); v.w = roundtf(v.w);
        out[i] = v;
    }
}

// ---------------- tf32 tensor-core GEMM: C = A(MxK) @ B(KxN), row-major ---
// A and B must already be tf32-rounded. 128x128 block tile, BK=32,
// 128 threads (4 warps as 2x2), warp tile 64x64, double-buffered cp.async,
// 2 CTAs/SM. Requires M % 128 == 0, K % 32 == 0.
#define TBM 128
#define TBN 128
#define TBK 32
#define AS_STR 36
#define BS_STR 136
#define AS_ELE (TBM * AS_STR)
#define BS_ELE (TBK * BS_STR)
#define TG_SMEM ((2 * AS_ELE + 2 * BS_ELE) * 4)

__global__ __launch_bounds__(128, 2) void tgemm_k(
    const float* __restrict__ A, const float* __restrict__ B,
    float* __restrict__ C, int M, int N, int K)
{
    extern __shared__ float sm[];
    float* As[2] = {sm, sm + AS_ELE};
    float* Bs[2] = {sm + 2 * AS_ELE, sm + 2 * AS_ELE + BS_ELE};

    const int n0 = blockIdx.x * TBN;
    const int m0 = blockIdx.y * TBM;
    const int tid  = threadIdx.x;
    const int lane = tid & 31;
    const int warp = tid >> 5;
    const int wm = warp & 1;
    const int wn = warp >> 1;
    const int g  = lane >> 2;
    const int tg = lane & 3;

    const int aRow  = tid >> 3;
    const int aCol4 = (tid & 7) * 4;
    const int bRow  = tid >> 5;
    const int bCol  = (tid & 31) * 4;
    const int bColC = (n0 + bCol < N) ? (n0 + bCol) : (N - 4);

    float acc[4][8][4];
#pragma unroll
    for (int i = 0; i < 4; i++)
#pragma unroll
        for (int j = 0; j < 8; j++)
#pragma unroll
            for (int e = 0; e < 4; e++) acc[i][j][e] = 0.f;

    const int nt = K / TBK;

    {
        const float* Asrc = A + (size_t)(m0 + aRow) * K + aCol4;
        float* Adst = As[0] + aRow * AS_STR + aCol4;
#pragma unroll
        for (int s = 0; s < 8; s++)
            cpasync16(Adst + s * 16 * AS_STR, Asrc + (size_t)s * 16 * K);
        const float* Bsrc = B + (size_t)bRow * N + bColC;
        float* Bdst = Bs[0] + bRow * BS_STR + bCol;
#pragma unroll
        for (int s = 0; s < 8; s++)
            cpasync16(Bdst + s * 4 * BS_STR, Bsrc + (size_t)s * 4 * N);
        CP_COMMIT();
    }

    for (int t = 0; t < nt; t++) {
        const int buf = t & 1;
        if (t + 1 < nt) {
            const int kn = (t + 1) * TBK;
            const float* Asrc = A + (size_t)(m0 + aRow) * K + kn + aCol4;
            float* Adst = As[buf ^ 1] + aRow * AS_STR + aCol4;
#pragma unroll
            for (int s = 0; s < 8; s++)
                cpasync16(Adst + s * 16 * AS_STR, Asrc + (size_t)s * 16 * K);
            const float* Bsrc = B + (size_t)(kn + bRow) * N + bColC;
            float* Bdst = Bs[buf ^ 1] + bRow * BS_STR + bCol;
#pragma unroll
            for (int s = 0; s < 8; s++)
                cpasync16(Bdst + s * 4 * BS_STR, Bsrc + (size_t)s * 4 * N);
            CP_COMMIT();
            CP_WAIT(1);
        } else {
            CP_WAIT(0);
        }
        __syncthreads();

        const float* Ab = As[buf];
        const float* Bb = Bs[buf];
#pragma unroll
        for (int kk = 0; kk < 4; kk++) {
            const int kr = kk * 8;
            unsigned af[4][4], bf[8][2];
#pragma unroll
            for (int i = 0; i < 4; i++) {
                const int r = wm * 64 + i * 16;
                af[i][0] = __float_as_uint(Ab[(r + g) * AS_STR + kr + tg]);
                af[i][1] = __float_as_uint(Ab[(r + g + 8) * AS_STR + kr + tg]);
                af[i][2] = __float_as_uint(Ab[(r + g) * AS_STR + kr + tg + 4]);
                af[i][3] = __float_as_uint(Ab[(r + g + 8) * AS_STR + kr + tg + 4]);
            }
#pragma unroll
            for (int j = 0; j < 8; j++) {
                const int cb = wn * 64 + j * 8;
                bf[j][0] = __float_as_uint(Bb[(kr + tg) * BS_STR + cb + g]);
                bf[j][1] = __float_as_uint(Bb[(kr + tg + 4) * BS_STR + cb + g]);
            }
#pragma unroll
            for (int i = 0; i < 4; i++)
#pragma unroll
                for (int j = 0; j < 8; j++)
                    mma_tf32(acc[i][j], af[i], bf[j]);
        }
        __syncthreads();
    }

#pragma unroll
    for (int i = 0; i < 4; i++) {
        const int r0 = m0 + wm * 64 + i * 16 + g;
#pragma unroll
        for (int j = 0; j < 8; j++) {
            const int c = n0 + wn * 64 + j * 8 + 2 * tg;
            if (c < N) {
                *(float2*)(C + (size_t)r0 * N + c) = make_float2(acc[i][j][0], acc[i][j][1]);
                *(float2*)(C + (size_t)(r0 + 8) * N + c) = make_float2(acc[i][j][2], acc[i][j][3]);
            }
        }
    }
}

// ---------------- RMSNorm (tf32-rounded output) --------------------------
__global__ void rmsnorm_k(const float* in, float* out, const float* __restrict__ w,
                          int cols, int in_stride, int out_stride)
{
    const int row = blockIdx.x;
    const float* xi = in + (size_t)row * in_stride;
    float s = 0.f;
    for (int c = threadIdx.x; c < cols; c += blockDim.x) {
        float v = xi[c];
        s += v * v;
    }
    __shared__ float red[8];
#pragma unroll
    for (int o = 16; o > 0; o >>= 1) s += __shfl_down_sync(0xffffffffu, s, o);
    int warp = threadIdx.x >> 5, lane = threadIdx.x & 31;
    if (lane == 0) red[warp] = s;
    __syncthreads();
    if (warp == 0) {
        s = (lane < (blockDim.x >> 5)) ? red[lane] : 0.f;
#pragma unroll
        for (int o = 4; o > 0; o >>= 1) s += __shfl_down_sync(0xffffffffu, s, o);
        if (lane == 0) red[0] = s;
    }
    __syncthreads();
    float r = rsqrtf(red[0] / (float)cols + 1e-6f);
    float* yo = out + (size_t)row * out_stride;
    for (int c = threadIdx.x; c < cols; c += blockDim.x)
        yo[c] = roundtf(xi[c] * r * w[c]);
}

// ---------------- RoPE ---------------------------------------------------
__global__ void rope_table_k(float* ct, float* st)
{
    int s = blockIdx.x, i = threadIdx.x;
    double inv = exp(-((double)(2 * i) / 64.0) * log(10000.0));
    double ang = (double)s * inv;
    ct[s * 32 + i] = (float)cos(ang);
    st[s * 32 + i] = (float)sin(ang);
}

__global__ void rope_q_k(float* Q, const float* __restrict__ ct, const float* __restrict__ st)
{
    int bs = blockIdx.x;
    int s = bs & (SS - 1);
    int i = threadIdx.x;
    int h = threadIdx.y;
    size_t base = ((size_t)bs * HH + h) * QH + NOPE;
    float c = ct[s * 32 + i], sn = st[s * 32 + i];
    float x1 = Q[base + i], x2 = Q[base + 32 + i];
    Q[base + i]      = x1 * c - x2 * sn;
    Q[base + 32 + i] = x2 * c + x1 * sn;
}

__global__ void rope_k_k(const float* __restrict__ CKV, float* KPE,
                         const float* __restrict__ ct, const float* __restrict__ st)
{
    int bs = blockIdx.x;
    int s = bs & (SS - 1);
    int i = threadIdx.x;
    const float* src = CKV + (size_t)bs * (KV_RANK + ROPE_D) + KV_RANK;
    float c = ct[s * 32 + i], sn = st[s * 32 + i];
    float x1 = src[i], x2 = src[32 + i];
    KPE[(size_t)bs * ROPE_D + i]      = x1 * c - x2 * sn;
    KPE[(size_t)bs * ROPE_D + 32 + i] = x2 * c + x1 * sn;
}

// ---------------- tf32 tensor-core causal flash attention ----------------
#define FBM 128
#define FBN 64
#define KS_STR 196
#define VS_STR 136
#define PS_STR 68
#define FLASH_SMEM ((FBN * KS_STR + FBN * VS_STR + FBM * PS_STR) * 4)

__global__ __launch_bounds__(256) void flash_k(
    const float* __restrict__ Q, const float* __restrict__ KV,
    const float* __restrict__ KPE, float* __restrict__ O)
{
    extern __shared__ unsigned smu[];
    unsigned* Ks = smu;                       // [64][196]
    unsigned* Vs = smu + FBN * KS_STR;        // [64][136]
    unsigned* Ps = Vs + FBN * VS_STR;         // [128][68]

    const int q0 = blockIdx.x * FBM;
    const int h = blockIdx.y;
    const int b = blockIdx.z;
    const int t = threadIdx.x;
    const int warp = t >> 5;
    const int lane = t & 31;
    const int g = lane >> 2;
    const int tg = lane & 3;
    const int row0 = warp * 16 + g;
    const float scale = rsqrtf((float)QH);

    unsigned aq[24][4];
    {
        const float* qp0 = Q + ((size_t)(b * SS + q0 + row0) * HH + h) * QH;
        const float* qp1 = qp0 + (size_t)8 * HH * QH;
#pragma unroll
        for (int kc = 0; kc < 24; kc++) {
            aq[kc][0] = f2tf32(qp0[kc * 8 + tg] * scale);
            aq[kc][1] = f2tf32(qp1[kc * 8 + tg] * scale);
            aq[kc][2] = f2tf32(qp0[kc * 8 + tg + 4] * scale);
            aq[kc][3] = f2tf32(qp1[kc * 8 + tg + 4] * scale);
        }
    }

    float oacc[16][4];
#pragma unroll
    for (int i = 0; i < 16; i++)
#pragma unroll
        for (int e = 0; e < 4; e++) oacc[i][e] = 0.f;
    float m0 = -3.0e38f, m1 = -3.0e38f, l0 = 0.f, l1 = 0.f;

    const int lr = t >> 2;
    const int q4 = t & 3;

    for (int k0 = 0; k0 < q0 + FBM; k0 += FBN) {
        __syncthreads();
        {
            const float4* kn = (const float4*)(KV + ((size_t)(b * SS + k0 + lr) * HH + h) * KVH);
            const float4* kp = (const float4*)(KPE + (size_t)(b * SS + k0 + lr) * ROPE_D);
#pragma unroll
            for (int i = 0; i < 12; i++) {
                int d4 = q4 * 12 + i;
                float4 v = (d4 < 32) ? kn[d4] : kp[d4 - 32];
                unsigned u[4] = {f2tf32(v.x), f2tf32(v.y), f2tf32(v.z), f2tf32(v.w)};
                *(uint4*)&Ks[lr * KS_STR + d4 * 4] = *(uint4*)u;
            }
#pragma unroll
            for (int i = 0; i < 8; i++) {
                int d4 = q4 * 8 + i;
                float4 v = kn[32 + d4];
                unsigned u[4] = {f2tf32(v.x), f2tf32(v.y), f2tf32(v.z), f2tf32(v.w)};
                *(uint4*)&Vs[lr * VS_STR + d4 * 4] = *(uint4*)u;
            }
        }
        __syncthreads();

        if (k0 > q0 + warp * 16 + 15) continue;

        float c[8][4];
#pragma unroll
        for (int nb = 0; nb < 8; nb++) {
#pragma unroll
            for (int e = 0; e < 4; e++) c[nb][e] = 0.f;
            const unsigned* krow = &Ks[(nb * 8 + g) * KS_STR];
#pragma unroll
            for (int kc = 0; kc < 24; kc++) {
                unsigned bf[2] = {krow[kc * 8 + tg], krow[kc * 8 + tg + 4]};
                mma_tf32(c[nb], aq[kc], bf);
            }
        }

        if (k0 + FBN - 1 > q0 + warp * 16) {
            const int r0g = q0 + warp * 16 + g;
#pragma unroll
            for (int nb = 0; nb < 8; nb++) {
                int col = k0 + nb * 8 + 2 * tg;
                if (col     > r0g)     c[nb][0] = -3.0e38f;
                if (col + 1 > r0g)     c[nb][1] = -3.0e38f;
                if (col     > r0g + 8) c[nb][2] = -3.0e38f;
                if (col + 1 > r0g + 8) c[nb][3] = -3.0e38f;
            }
        }

        float tm0 = -3.0e38f, tm1 = -3.0e38f;
#pragma unroll
        for (int nb = 0; nb < 8; nb++) {
            tm0 = fmaxf(tm0, fmaxf(c[nb][0], c[nb][1]));
            tm1 = fmaxf(tm1, fmaxf(c[nb][2], c[nb][3]));
        }
        tm0 = fmaxf(tm0, __shfl_xor_sync(0xffffffffu, tm0, 1));
        tm0 = fmaxf(tm0, __shfl_xor_sync(0xffffffffu, tm0, 2));
        tm1 = fmaxf(tm1, __shfl_xor_sync(0xffffffffu, tm1, 1));
        tm1 = fmaxf(tm1, __shfl_xor_sync(0xffffffffu, tm1, 2));

        float nm0 = fmaxf(m0, tm0), nm1 = fmaxf(m1, tm1);
        float co0 = __expf(m0 - nm0), co1 = __expf(m1 - nm1);
        l0 *= co0; l1 *= co1;
#pragma unroll
        for (int nb = 0; nb < 16; nb++) {
            oacc[nb][0] *= co0; oacc[nb][1] *= co0;
            oacc[nb][2] *= co1; oacc[nb][3] *= co1;
        }
        m0 = nm0; m1 = nm1;

        unsigned* ps0 = &Ps[(size_t)(warp * 16 + g) * PS_STR];
        unsigned* ps1 = &Ps[(size_t)(warp * 16 + g + 8) * PS_STR];
        float ls0 = 0.f, ls1 = 0.f;
#pragma unroll
        for (int nb = 0; nb < 8; nb++) {
            float p0 = __expf(c[nb][0] - nm0);
            float p1 = __expf(c[nb][1] - nm0);
            float p2 = __expf(c[nb][2] - nm1);
            float p3 = __expf(c[nb][3] - nm1);
            ls0 += p0 + p1; ls1 += p2 + p3;
            ps0[nb * 8 + 2 * tg]     = f2tf32(p0);
            ps0[nb * 8 + 2 * tg + 1] = f2tf32(p1);
            ps1[nb * 8 + 2 * tg]     = f2tf32(p2);
            ps1[nb * 8 + 2 * tg + 1] = f2tf32(p3);
        }
        ls0 += __shfl_xor_sync(0xffffffffu, ls0, 1);
        ls0 += __shfl_xor_sync(0xffffffffu, ls0, 2);
        ls1 += __shfl_xor_sync(0xffffffffu, ls1, 1);
        ls1 += __shfl_xor_sync(0xffffffffu, ls1, 2);
        l0 += ls0; l1 += ls1;

        __syncwarp();

#pragma unroll
        for (int kc = 0; kc < 8; kc++) {
            unsigned ap[4] = {ps0[kc * 8 + tg], ps1[kc * 8 + tg],
                              ps0[kc * 8 + tg + 4], ps1[kc * 8 + tg + 4]};
#pragma unroll
            for (int nb = 0; nb < 16; nb++) {
                unsigned bv[2] = {Vs[(kc * 8 + tg) * VS_STR + nb * 8 + g],
                                  Vs[(kc * 8 + tg + 4) * VS_STR + nb * 8 + g]};
                mma_tf32(oacc[nb], ap, bv);
            }
        }
        __syncwarp();
    }

    // epilogue (tf32-rounded: feeds the final GEMM directly)
    float inv0 = 1.f / l0, inv1 = 1.f / l1;
    float* o0 = O + ((size_t)(b * SS + q0 + row0) * HH + h) * VD;
    float* o1 = o0 + (size_t)8 * HH * VD;
#pragma unroll
    for (int nb = 0; nb < 16; nb++) {
        *(float2*)(o0 + nb * 8 + 2 * tg) = make_float2(roundtf(oacc[nb][0] * inv0),
                                                       roundtf(oacc[nb][1] * inv0));
        *(float2*)(o1 + nb * 8 + 2 * tg) = make_float2(roundtf(oacc[nb][2] * inv1),
                                                       roundtf(oacc[nb][3] * inv1));
    }
}

// ---------------- host launcher ------------------------------------------
extern "C" void kernel_launch(void* const* d_in, const int* in_sizes, int n_in,
                              void* d_out, int out_size)
{
    const float* x         = (const float*)d_in[0];
    const float* w_dq      = (const float*)d_in[1];
    const float* q_a_norm  = (const float*)d_in[2];
    const float* w_uq      = (const float*)d_in[3];
    const float* w_dkv     = (const float*)d_in[4];
    const float* kv_a_norm = (const float*)d_in[5];
    const float* w_ukv     = (const float*)d_in[6];
    const float* w_o       = (const float*)d_in[7];
    float* out = (float*)d_out;

    float *cq, *q, *ckv, *kva, *kpe, *kv, *o, *ct, *st;
    float *xr, *wdq, *wuq, *wdkv, *wukv, *wo;
    cudaGetSymbolAddress((void**)&cq,  g_cq);
    cudaGetSymbolAddress((void**)&q,   g_q);
    cudaGetSymbolAddress((void**)&ckv, g_ckv);
    cudaGetSymbolAddress((void**)&kva, g_kva);
    cudaGetSymbolAddress((void**)&kpe, g_kpe);
    cudaGetSymbolAddress((void**)&kv,  g_kv);
    cudaGetSymbolAddress((void**)&o,   g_o);
    cudaGetSymbolAddress((void**)&ct,  g_cos);
    cudaGetSymbolAddress((void**)&st,  g_sin);
    cudaGetSymbolAddress((void**)&xr,   g_xr);
    cudaGetSymbolAddress((void**)&wdq,  g_wdq);
    cudaGetSymbolAddress((void**)&wuq,  g_wuq);
    cudaGetSymbolAddress((void**)&wdkv, g_wdkv);
    cudaGetSymbolAddress((void**)&wukv, g_wukv);
    cudaGetSymbolAddress((void**)&wo,   g_wo);

    cudaFuncSetAttribute(tgemm_k, cudaFuncAttributeMaxDynamicSharedMemorySize, TG_SMEM);
    cudaFuncSetAttribute(flash_k, cudaFuncAttributeMaxDynamicSharedMemorySize, FLASH_SMEM);

    rope_table_k<<<SS, 32>>>(ct, st);

    // pre-round GEMM operands to tf32
    cvt_k<<<592, 256>>>((const float4*)x,     (float4*)xr,   RTOT * DD / 4);
    cvt_k<<<592, 256>>>((const float4*)w_dq,  (float4*)wdq,  DD * Q_RANK / 4);
    cvt_k<<<592, 256>>>((const float4*)w_uq,  (float4*)wuq,  Q_RANK * HH * QH / 4);
    cvt_k<<<592, 256>>>((const float4*)w_dkv, (float4*)wdkv, DD * (KV_RANK + ROPE_D) / 4);
    cvt_k<<<592, 256>>>((const float4*)w_ukv, (float4*)wukv, KV_RANK * HH * KVH / 4);
    cvt_k<<<592, 256>>>((const float4*)w_o,   (float4*)wo,   HH * VD * DD / 4);

    // q path
    tgemm_k<<<dim3(Q_RANK / TBN, RTOT / TBM), 128, TG_SMEM>>>(xr, wdq, cq, RTOT, Q_RANK, DD);
    rmsnorm_k<<<RTOT, 256>>>(cq, cq, q_a_norm, Q_RANK, Q_RANK, Q_RANK);
    tgemm_k<<<dim3((HH * QH) / TBN, RTOT / TBM), 128, TG_SMEM>>>(cq, wuq, q, RTOT, HH * QH, Q_RANK);

    // kv path
    tgemm_k<<<dim3((KV_RANK + ROPE_D + TBN - 1) / TBN, RTOT / TBM), 128, TG_SMEM>>>(
        xr, wdkv, ckv, RTOT, KV_RANK + ROPE_D, DD);
    rmsnorm_k<<<RTOT, 256>>>(ckv, kva, kv_a_norm, KV_RANK, KV_RANK + ROPE_D, KV_RANK);
    tgemm_k<<<dim3((HH * KVH) / TBN, RTOT / TBM), 128, TG_SMEM>>>(kva, wukv, kv, RTOT, HH * KVH, KV_RANK);

    // RoPE
    rope_q_k<<<RTOT, dim3(32, HH)>>>(q, ct, st);
    rope_k_k<<<RTOT, 32>>>(ckv, kpe, ct, st);

    // attention
    flash_k<<<dim3(SS / FBM, HH, BB), 256, FLASH_SMEM>>>(q, kv, kpe, o);

    // output projection
    tgemm_k<<<dim3(DD / TBN, RTOT / TBM), 128, TG_SMEM>>>(o, wo, out, RTOT, DD, HH * VD);
}